// round 14
// baseline (speedup 1.0000x reference)
#include <cuda_runtime.h>
#include <cuda_bf16.h>
#include <cstdint>

// Problem constants
#define B_   16
#define L_   1024
#define D_   512
#define H_   8
#define DK_  64
#define M_ROWS   (B_ * L_)            // 16384
#define TOK_ELEMS  (B_ * L_ * D_)     // 8388608
#define PROJ_ELEMS (B_ * H_ * L_ * DK_) // 8388608
#define OUT0_ELEMS ((size_t)B_ * L_ * D_)

// ---------------- scratch (device globals) ------------------------------------
__device__ __nv_bfloat16 g_Ab[6][TOK_ELEMS];
__device__ __nv_bfloat16 g_As[6][TOK_ELEMS];
__device__ __nv_bfloat16 g_Wb[4][H_ * DK_ * D_];
__device__ __nv_bfloat16 g_Ws[4][H_ * DK_ * D_];
__device__ __nv_bfloat16 g_WVb[DK_ * D_];
__device__ __nv_bfloat16 g_WVs[DK_ * D_];

__device__ float g_ss[PROJ_ELEMS];
__device__ float g_cs[PROJ_ELEMS];
__device__ float g_st[PROJ_ELEMS];
__device__ float g_ct[PROJ_ELEMS];
__device__ float g_v[B_ * L_ * DK_];
__device__ float g_head[PROJ_ELEMS];
__device__ __nv_bfloat16 g_qb[PROJ_ELEMS];
__device__ __nv_bfloat16 g_qs[PROJ_ELEMS];
__device__ __nv_bfloat16 g_kb[PROJ_ELEMS];
__device__ __nv_bfloat16 g_ks[PROJ_ELEMS];
__device__ uint32_t g_vd[B_ * DK_ * L_];
__device__ uint32_t g_vc[B_ * DK_ * L_];

// ---------------- PTX helpers --------------------------------------------------
__device__ __forceinline__ uint32_t smem_u32(const void* p) {
    uint32_t a;
    asm("{ .reg .u64 t; cvta.to.shared.u64 t, %1; cvt.u32.u64 %0, t; }" : "=r"(a) : "l"(p));
    return a;
}
#define CP_ASYNC16(dst, src) \
    asm volatile("cp.async.cg.shared.global [%0], [%1], 16;" :: "r"(dst), "l"(src) : "memory")
#define CP_COMMIT() asm volatile("cp.async.commit_group;" ::: "memory")
#define CP_WAIT0()  asm volatile("cp.async.wait_group 0;" ::: "memory")
#define CP_WAIT1()  asm volatile("cp.async.wait_group 1;" ::: "memory")

#define LDSM_X4(r0, r1, r2, r3, addr) \
    asm volatile("ldmatrix.sync.aligned.m8n8.x4.shared.b16 {%0,%1,%2,%3}, [%4];" \
        : "=r"(r0), "=r"(r1), "=r"(r2), "=r"(r3) : "r"(addr))

#define MMA_BF16(c, a0, a1, a2, a3, b0, b1) \
    asm volatile("mma.sync.aligned.m16n8k16.row.col.f32.bf16.bf16.f32 " \
        "{%0,%1,%2,%3},{%4,%5,%6,%7},{%8,%9},{%0,%1,%2,%3};" \
        : "+f"((c)[0]), "+f"((c)[1]), "+f"((c)[2]), "+f"((c)[3]) \
        : "r"(a0), "r"(a1), "r"(a2), "r"(a3), "r"(b0), "r"(b1))

__device__ __forceinline__ void bf16_split(float x, __nv_bfloat16& big, __nv_bfloat16& sml) {
    big = __float2bfloat16_rn(x);
    sml = __float2bfloat16_rn(x - __bfloat162float(big));
}
__device__ __forceinline__ uint16_t bf_bits(__nv_bfloat16 v) {
    uint16_t u; *(__nv_bfloat16*)&u = v; return u;
}
__device__ __forceinline__ uint32_t bf_pack(__nv_bfloat16 lo, __nv_bfloat16 hi) {
    return (uint32_t)bf_bits(lo) | ((uint32_t)bf_bits(hi) << 16);
}

// ---------------- LayerNorm (emits split bf16) ---------------------------------
__global__ void ln_kernel(const float* __restrict__ sat, const float* __restrict__ ts,
                          const float* __restrict__ gs, const float* __restrict__ bs,
                          const float* __restrict__ gt, const float* __restrict__ bt)
{
    int rid = blockIdx.x;
    const float* src; __nv_bfloat16 *db, *ds; const float* g; const float* bb;
    if (rid < M_ROWS) {
        src = sat + (size_t)rid * D_;
        db = g_Ab[0] + (size_t)rid * D_;  ds = g_As[0] + (size_t)rid * D_;
        g = gs; bb = bs;
    } else {
        int r = rid - M_ROWS;
        src = ts + (size_t)r * D_;
        db = g_Ab[1] + (size_t)r * D_;    ds = g_As[1] + (size_t)r * D_;
        g = gt; bb = bt;
    }
    int t = threadIdx.x;
    float4 x = ((const float4*)src)[t];
    float s  = x.x + x.y + x.z + x.w;
    float sq = x.x*x.x + x.y*x.y + x.z*x.z + x.w*x.w;
    #pragma unroll
    for (int o = 16; o; o >>= 1) {
        s  += __shfl_xor_sync(0xFFFFFFFFu, s,  o);
        sq += __shfl_xor_sync(0xFFFFFFFFu, sq, o);
    }
    __shared__ float ws[4], wq[4];
    if ((t & 31) == 0) { ws[t >> 5] = s; wq[t >> 5] = sq; }
    __syncthreads();
    s  = ws[0] + ws[1] + ws[2] + ws[3];
    sq = wq[0] + wq[1] + wq[2] + wq[3];
    float m   = s * (1.0f / D_);
    float var = sq * (1.0f / D_) - m * m;
    float inv = rsqrtf(var + 1e-5f);
    float4 g4 = ((const float4*)g)[t];
    float4 b4 = ((const float4*)bb)[t];
    float o[4];
    o[0] = (x.x - m) * inv * g4.x + b4.x;
    o[1] = (x.y - m) * inv * g4.y + b4.y;
    o[2] = (x.z - m) * inv * g4.z + b4.z;
    o[3] = (x.w - m) * inv * g4.w + b4.w;
    __nv_bfloat16 big[4], sml[4];
    #pragma unroll
    for (int i = 0; i < 4; i++) bf16_split(o[i], big[i], sml[i]);
    *(uint2*)&db[t * 4] = *(uint2*)big;
    *(uint2*)&ds[t * 4] = *(uint2*)sml;
}

// ---------------- merged split (all 4 pos-embedding tensors) -------------------
__global__ void split4_kernel(const float* __restrict__ x0, const float* __restrict__ x1,
                              const float* __restrict__ x2, const float* __restrict__ x3)
{
    int which = blockIdx.y;
    const float* x = (which == 0) ? x0 : (which == 1) ? x1 : (which == 2) ? x2 : x3;
    __nv_bfloat16* big = g_Ab[2 + which];
    __nv_bfloat16* sml = g_As[2 + which];
    int i = blockIdx.x * blockDim.x + threadIdx.x;
    float4 v = ((const float4*)x)[i];
    __nv_bfloat16 b[4], s[4];
    bf16_split(v.x, b[0], s[0]);
    bf16_split(v.y, b[1], s[1]);
    bf16_split(v.z, b[2], s[2]);
    bf16_split(v.w, b[3], s[3]);
    *(uint2*)&big[(size_t)i * 4] = *(uint2*)b;
    *(uint2*)&sml[(size_t)i * 4] = *(uint2*)s;
}

// ---------------- weight transpose + split -------------------------------------
__global__ void transpose_w(const float* __restrict__ W,
                            __nv_bfloat16* __restrict__ Wb, __nv_bfloat16* __restrict__ Wsml)
{
    __shared__ float t[64][65];
    int h = blockIdx.x, k0 = blockIdx.y * 64;
    const float* Wp = W + (size_t)h * (D_ * DK_);
    #pragma unroll
    for (int i = 0; i < 16; i++) {
        int e = threadIdx.x + i * 256;
        int r = e >> 6, c = e & 63;
        t[r][c] = Wp[(size_t)(k0 + r) * 64 + c];
    }
    __syncthreads();
    #pragma unroll
    for (int i = 0; i < 16; i++) {
        int e = threadIdx.x + i * 256;
        int n = e >> 6, kk = e & 63;
        __nv_bfloat16 big, sml;
        bf16_split(t[kk][n], big, sml);
        size_t off = (size_t)h * (DK_ * D_) + (size_t)n * 512 + k0 + kk;
        Wb[off] = big;
        Wsml[off] = sml;
    }
}

// ---------------- V prep ---------------------------------------------------------
__global__ void vprep_kernel()
{
    __shared__ float t[64][65];
    int b = blockIdx.x, k0 = blockIdx.y * 64;
    int tid = threadIdx.x;
    #pragma unroll
    for (int i = 0; i < 16; i++) {
        int e = tid + i * 256;
        int k = e >> 6, d = e & 63;
        t[k][d] = g_v[((size_t)b * L_ + k0 + k) * 64 + d];
    }
    __syncthreads();
    #pragma unroll
    for (int i = 0; i < 16; i++) {
        int e = tid + i * 256;
        int d = e >> 6, k = e & 63;
        __nv_bfloat16 vb, vs;
        bf16_split(t[k][d], vb, vs);
        size_t off = ((size_t)b * DK_ + d) * L_ + k0 + k;
        uint32_t ub = bf_bits(vb), us = bf_bits(vs);
        g_vd[off] = ub | (ub << 16);
        g_vc[off] = us;
    }
}

// ---------------- 3xBF16 projection GEMM (R13, proven) --------------------------
#define GSTR 144
#define GA_SZ (128 * GSTR)
#define GB_SZ (64 * GSTR)
#define GSTG (GA_SZ + GB_SZ)
#define GEMM_SMEM (2 * GSTG)

__global__ void __launch_bounds__(256) gemm_bf16(const __nv_bfloat16* __restrict__ Ab,
                                                 const __nv_bfloat16* __restrict__ As,
                                                 const __nv_bfloat16* __restrict__ Bb,
                                                 const __nv_bfloat16* __restrict__ Bs,
                                                 const float* __restrict__ bias,
                                                 float* __restrict__ C,
                                                 const float* __restrict__ cosA,
                                                 const float* __restrict__ sinA,
                                                 __nv_bfloat16* __restrict__ outB,
                                                 __nv_bfloat16* __restrict__ outS,
                                                 int mode)
{
    extern __shared__ __align__(16) char smraw[];
    uint32_t sb = smem_u32(smraw);
    int tid = threadIdx.x, lane = tid & 31, wid = tid >> 5;
    int warp_m = wid >> 1, warp_n = wid & 1;
    int m0 = blockIdx.x * 128, by = blockIdx.y, n0 = by * 64;

    uint32_t laneA = (uint32_t)((warp_m * 32 + (lane & 7) + ((lane >> 3) & 1) * 8) * GSTR + (lane >> 4) * 16);
    uint32_t laneB = (uint32_t)((warp_n * 32 + (lane & 7) + ((lane >> 3) & 1) * 8) * GSTR + (lane >> 4) * 16);

    float c[8][4];
    #pragma unroll
    for (int i = 0; i < 8; i++)
        #pragma unroll
        for (int j = 0; j < 4; j++) c[i][j] = 0.0f;

    auto load_stage = [&](int s, int k0) {
        uint32_t base = sb + s * GSTG;
        #pragma unroll
        for (int i = 0; i < 4; i++) {
            int e = tid + i * 256, r = e >> 3, cc = e & 7;
            const __nv_bfloat16* src = (cc < 4)
                ? Ab + (size_t)(m0 + r) * 512 + k0 + cc * 8
                : As + (size_t)(m0 + r) * 512 + k0 + (cc - 4) * 8;
            CP_ASYNC16(base + (uint32_t)(r * GSTR + cc * 16), src);
        }
        #pragma unroll
        for (int i = 0; i < 2; i++) {
            int e = tid + i * 256, r = e >> 3, cc = e & 7;
            const __nv_bfloat16* src = (cc < 4)
                ? Bb + (size_t)(n0 + r) * 512 + k0 + cc * 8
                : Bs + (size_t)(n0 + r) * 512 + k0 + (cc - 4) * 8;
            CP_ASYNC16(base + GA_SZ + (uint32_t)(r * GSTR + cc * 16), src);
        }
    };

    auto compute = [&](int s) {
        uint32_t abase = sb + s * GSTG + laneA;
        uint32_t bbase = sb + s * GSTG + GA_SZ + laneB;
        #pragma unroll
        for (int ks = 0; ks < 2; ks++) {
            uint32_t aB[2][4], aS[2][4], bB[2][4], bS[2][4];
            #pragma unroll
            for (int mt = 0; mt < 2; mt++) {
                LDSM_X4(aB[mt][0], aB[mt][1], aB[mt][2], aB[mt][3], abase + mt * (16 * GSTR) + ks * 32);
                LDSM_X4(aS[mt][0], aS[mt][1], aS[mt][2], aS[mt][3], abase + mt * (16 * GSTR) + 64 + ks * 32);
            }
            #pragma unroll
            for (int nt = 0; nt < 2; nt++) {
                LDSM_X4(bB[nt][0], bB[nt][1], bB[nt][2], bB[nt][3], bbase + nt * (16 * GSTR) + ks * 32);
                LDSM_X4(bS[nt][0], bS[nt][1], bS[nt][2], bS[nt][3], bbase + nt * (16 * GSTR) + 64 + ks * 32);
            }
            #pragma unroll
            for (int mt = 0; mt < 2; mt++)
                #pragma unroll
                for (int j = 0; j < 4; j++) {
                    int nt = j >> 1, hh = j & 1;
                    float* cc = c[mt * 4 + j];
                    MMA_BF16(cc, aS[mt][0], aS[mt][1], aS[mt][2], aS[mt][3], bB[nt][hh], bB[nt][2 + hh]);
                    MMA_BF16(cc, aB[mt][0], aB[mt][1], aB[mt][2], aB[mt][3], bS[nt][hh], bS[nt][2 + hh]);
                    MMA_BF16(cc, aB[mt][0], aB[mt][1], aB[mt][2], aB[mt][3], bB[nt][hh], bB[nt][2 + hh]);
                }
        }
    };

    load_stage(0, 0);
    CP_COMMIT();
    for (int ck = 0; ck < 16; ck++) {
        if (ck < 15) {
            load_stage((ck + 1) & 1, (ck + 1) * 32);
            CP_COMMIT();
            CP_WAIT1();
        } else {
            CP_WAIT0();
        }
        __syncthreads();
        compute(ck & 1);
        __syncthreads();
    }

    int r_lane = lane >> 2, c_lane = (lane & 3) * 2;
    #pragma unroll
    for (int i = 0; i < 2; i++) {
        #pragma unroll
        for (int j = 0; j < 4; j++) {
            float* cc = c[i * 4 + j];
            int nc = warp_n * 32 + j * 8 + c_lane;
            int mrow = m0 + warp_m * 32 + i * 16 + r_lane;
            float2 bb2;
            size_t base0, base1;
            if (mode == 1) {
                bb2 = *(const float2*)&bias[nc];
                base0 = (size_t)mrow * 64 + nc;
                base1 = (size_t)(mrow + 8) * 64 + nc;
            } else {
                bb2 = *(const float2*)&bias[by * 64 + nc];
                int b0r = mrow >> 10, l0r = mrow & 1023;
                int b1r = (mrow + 8) >> 10, l1r = (mrow + 8) & 1023;
                base0 = ((((size_t)(b0r * 8 + by)) << 10) + l0r) * 64 + nc;
                base1 = ((((size_t)(b1r * 8 + by)) << 10) + l1r) * 64 + nc;
            }
            float v00 = cc[0] + bb2.x, v01 = cc[1] + bb2.y;
            float v10 = cc[2] + bb2.x, v11 = cc[3] + bb2.y;
            if (mode == 2) {
                float2 cv0 = *(const float2*)&cosA[base0];
                float2 sv0 = *(const float2*)&sinA[base0];
                float2 cv1 = *(const float2*)&cosA[base1];
                float2 sv1 = *(const float2*)&sinA[base1];
                float o00 = v00 * cv0.x - v01 * sv0.x;
                float o01 = v01 * cv0.y + v00 * sv0.y;
                float o10 = v10 * cv1.x - v11 * sv1.x;
                float o11 = v11 * cv1.y + v10 * sv1.y;
                __nv_bfloat16 b0, s0, b1, s1;
                bf16_split(o00, b0, s0); bf16_split(o01, b1, s1);
                *(uint32_t*)&outB[base0] = bf_pack(b0, b1);
                *(uint32_t*)&outS[base0] = bf_pack(s0, s1);
                bf16_split(o10, b0, s0); bf16_split(o11, b1, s1);
                *(uint32_t*)&outB[base1] = bf_pack(b0, b1);
                *(uint32_t*)&outS[base1] = bf_pack(s0, s1);
            } else {
                float2 o0 = {v00, v01};
                float2 o1 = {v10, v11};
                *(float2*)&C[base0] = o0;
                *(float2*)&C[base1] = o1;
            }
        }
    }
}

// ---------------- attention: pipelined bf16x3 QK^T + packed-bf16 MMA PV ---------
#define QT  32
#define KT2 128                            // keys per K chunk
#define VT2 64                             // keys per V chunk
#define SCP 1028
#define STRK 144
#define STRV2 272                          // 64 keys * 4B + 16 pad
#define SC_BYTES   (QT * SCP * 4)          // 131584
#define KREG_OFF   SC_BYTES
#define KSTG (2 * KT2 * STRK)              // 36864 per stage (kb|ks)
#define VSTG (2 * VT2 * STRV2)             // 34816 per stage (vd|vc)
#define VHALF (VT2 * STRV2)                // 17408
#define KREG_BYTES (2 * KSTG)              // 73728
#define QREG_OFF   (KREG_OFF + KREG_BYTES)
#define QB_BYTES   (QT * STRK)
#define ATTN_SMEM  (QREG_OFF + 2 * QB_BYTES)   // 214528

__global__ void __launch_bounds__(256) attn_kernel(float* __restrict__ attn_out)
{
    extern __shared__ __align__(16) float smf[];
    float* sc  = smf;
    uint32_t* scu = (uint32_t*)smf;
    char*  kreg = (char*)smf + KREG_OFF;
    char*  qreg = (char*)smf + QREG_OFF;

    int tid = threadIdx.x, lane = tid & 31, wid = tid >> 5;
    int q0 = blockIdx.x * QT;
    int h  = blockIdx.y;
    int b  = blockIdx.z;
    size_t bh = (size_t)(b * H_ + h);

    uint32_t skb = smem_u32(kreg), sqb = smem_u32(qreg), ssb = smem_u32(sc);

    // q tile (32 rows x 64 bf16, big + small) via cp.async
    {
        int r = tid >> 3, cch = tid & 7;
        CP_ASYNC16(sqb + (uint32_t)(r * STRK + cch * 16),
                   &g_qb[((bh << 10) + q0 + r) * 64 + cch * 8]);
        CP_ASYNC16(sqb + (uint32_t)(QB_BYTES + r * STRK + cch * 16),
                   &g_qs[((bh << 10) + q0 + r) * 64 + cch * 8]);
    }

    // ---- K loader: chunk kt (128 keys) into stage s ----
    auto load_k = [&](int s, int kt) {
        uint32_t base = skb + s * KSTG;
        size_t kbase = ((bh << 10) + (size_t)kt * KT2) * 64;
        #pragma unroll
        for (int i = 0; i < 4; i++) {
            int e = tid + i * 256, r = e >> 3, cch = e & 7;
            CP_ASYNC16(base + (uint32_t)(r * STRK + cch * 16),
                       &g_kb[kbase + (size_t)r * 64 + cch * 8]);
            CP_ASYNC16(base + (uint32_t)(KT2 * STRK + r * STRK + cch * 16),
                       &g_ks[kbase + (size_t)r * 64 + cch * 8]);
        }
    };
    // ---- V loader: chunk vt (64 keys) into stage s ----
    auto load_v = [&](int s, int vt) {
        uint32_t base = skb + s * VSTG;
        const uint32_t* vdg = g_vd + ((size_t)b * DK_) * L_ + vt * VT2;
        const uint32_t* vcg = g_vc + ((size_t)b * DK_) * L_ + vt * VT2;
        #pragma unroll
        for (int i = 0; i < 4; i++) {
            int e = tid + i * 256, r = e >> 4, ch = e & 15;
            CP_ASYNC16(base + (uint32_t)(r * STRV2 + ch * 16),
                       vdg + (size_t)r * L_ + ch * 4);
            CP_ASYNC16(base + (uint32_t)(VHALF + r * STRV2 + ch * 16),
                       vcg + (size_t)r * L_ + ch * 4);
        }
    };

    // fragment lane offsets
    uint32_t aB0 = sqb + (uint32_t)(((lane & 7) + ((lane >> 3) & 1) * 8) * STRK + (lane >> 4) * 16);
    uint32_t aS0 = aB0 + QB_BYTES;
    uint32_t bOffK = (uint32_t)((wid * 16 + (lane & 7) + ((lane >> 3) & 1) * 8) * STRK + (lane >> 4) * 16);

    // ---- scores: 8 pipelined chunks of 128 keys; warp wid covers 16 keys ----
    load_k(0, 0); CP_COMMIT();
    load_k(1, 1); CP_COMMIT();
    for (int kt = 0; kt < 8; kt++) {
        if (kt == 7) { CP_WAIT0(); } else { CP_WAIT1(); }
        __syncthreads();
        int s = kt & 1;
        uint32_t bB0 = skb + s * KSTG + bOffK;
        uint32_t bS0 = bB0 + (uint32_t)(KT2 * STRK);

        float c[2][2][4];
        #pragma unroll
        for (int mt = 0; mt < 2; mt++)
            #pragma unroll
            for (int j = 0; j < 2; j++)
                #pragma unroll
                for (int e = 0; e < 4; e++) c[mt][j][e] = 0.0f;

        #pragma unroll
        for (int ks = 0; ks < 4; ks++) {
            uint32_t aB[2][4], aS[2][4], bB[4], bS[4];
            #pragma unroll
            for (int mt = 0; mt < 2; mt++) {
                LDSM_X4(aB[mt][0], aB[mt][1], aB[mt][2], aB[mt][3], aB0 + mt * (16 * STRK) + ks * 32);
                LDSM_X4(aS[mt][0], aS[mt][1], aS[mt][2], aS[mt][3], aS0 + mt * (16 * STRK) + ks * 32);
            }
            LDSM_X4(bB[0], bB[1], bB[2], bB[3], bB0 + ks * 32);
            LDSM_X4(bS[0], bS[1], bS[2], bS[3], bS0 + ks * 32);
            #pragma unroll
            for (int mt = 0; mt < 2; mt++)
                #pragma unroll
                for (int j = 0; j < 2; j++) {
                    float* cc = c[mt][j];
                    MMA_BF16(cc, aS[mt][0], aS[mt][1], aS[mt][2], aS[mt][3], bB[j], bB[2 + j]);
                    MMA_BF16(cc, aB[mt][0], aB[mt][1], aB[mt][2], aB[mt][3], bS[j], bS[2 + j]);
                    MMA_BF16(cc, aB[mt][0], aB[mt][1], aB[mt][2], aB[mt][3], bB[j], bB[2 + j]);
                }
        }
        int rr = lane >> 2, ccl = (lane & 3) * 2;
        #pragma unroll
        for (int mt = 0; mt < 2; mt++)
            #pragma unroll
            for (int j = 0; j < 2; j++) {
                int col = kt * KT2 + wid * 16 + j * 8 + ccl;
                int row0 = mt * 16 + rr;
                float2 o0 = {c[mt][j][0] * 0.125f, c[mt][j][1] * 0.125f};
                float2 o1 = {c[mt][j][2] * 0.125f, c[mt][j][3] * 0.125f};
                *(float2*)&sc[row0 * SCP + col]       = o0;
                *(float2*)&sc[(row0 + 8) * SCP + col] = o1;
            }
        __syncthreads();
        if (kt < 6) { load_k(kt & 1, kt + 2); CP_COMMIT(); }
    }

    // prefetch V stages 0,1 so softmax hides the loads
    load_v(0, 0); CP_COMMIT();
    load_v(1, 1); CP_COMMIT();

    // ---- softmax (rows wid*4..+3); packs (pb|ps) in place ----
    for (int rr = wid * 4; rr < wid * 4 + 4; rr++) {
        float vals[32];
        float mx = -1e30f;
        #pragma unroll
        for (int j = 0; j < 32; j++) {
            vals[j] = sc[rr * SCP + lane + 32 * j];
            mx = fmaxf(mx, vals[j]);
        }
        #pragma unroll
        for (int o = 16; o; o >>= 1) mx = fmaxf(mx, __shfl_xor_sync(0xFFFFFFFFu, mx, o));
        float s = 0.0f;
        #pragma unroll
        for (int j = 0; j < 32; j++) { vals[j] = __expf(vals[j] - mx); s += vals[j]; }
        #pragma unroll
        for (int o = 16; o; o >>= 1) s += __shfl_xor_sync(0xFFFFFFFFu, s, o);
        float inv = 1.0f / s;
        size_t obase = (((size_t)(b * L_ + q0 + rr) * H_ + h) << 10);
        #pragma unroll
        for (int j = 0; j < 32; j++) {
            float p = vals[j] * inv;
            attn_out[obase + lane + 32 * j] = p;
            __nv_bfloat16 pb, ps;
            bf16_split(p, pb, ps);
            scu[rr * SCP + lane + 32 * j] = bf_pack(pb, ps);
        }
    }

    // ---- head = P @ V (pipelined, 16 chunks of 64 keys) ----
    int mt = wid >> 2, nt = wid & 3;
    float acc[2][4];
    #pragma unroll
    for (int j = 0; j < 2; j++)
        #pragma unroll
        for (int e = 0; e < 4; e++) acc[j][e] = 0.0f;

    uint32_t aP0 = ssb + (uint32_t)((mt * 16 + (lane & 7) + ((lane >> 3) & 1) * 8) * (SCP * 4) + (lane >> 4) * 16);
    uint32_t vOff = (uint32_t)((nt * 16 + (lane & 7) + ((lane >> 3) & 1) * 8) * STRV2 + (lane >> 4) * 16);

    for (int vt = 0; vt < 16; vt++) {
        if (vt == 15) { CP_WAIT0(); } else { CP_WAIT1(); }
        __syncthreads();
        int s = vt & 1;
        uint32_t vD0 = skb + s * VSTG + vOff;
        uint32_t vC0 = vD0 + (uint32_t)VHALF;
        #pragma unroll
        for (int st = 0; st < 8; st++) {
            uint32_t a[4], bd[4], bc[4];
            LDSM_X4(a[0], a[1], a[2], a[3], aP0 + (uint32_t)(vt * 256 + st * 32));
            LDSM_X4(bd[0], bd[1], bd[2], bd[3], vD0 + st * 32);
            LDSM_X4(bc[0], bc[1], bc[2], bc[3], vC0 + st * 32);
            #pragma unroll
            for (int j = 0; j < 2; j++) {
                MMA_BF16(acc[j], a[0], a[1], a[2], a[3], bd[j], bd[2 + j]);
                MMA_BF16(acc[j], a[0], a[1], a[2], a[3], bc[j], bc[2 + j]);
            }
        }
        __syncthreads();
        if (vt < 14) { load_v(vt & 1, vt + 2); CP_COMMIT(); }
    }
    {
        int rr = lane >> 2, cl = (lane & 3) * 2;
        #pragma unroll
        for (int j = 0; j < 2; j++) {
            int col = nt * 16 + j * 8 + cl;
            int row0 = mt * 16 + rr;
            float2 o0 = {acc[j][0], acc[j][1]};
            float2 o1 = {acc[j][2], acc[j][3]};
            *(float2*)&g_head[((bh << 10) + q0 + row0) * 64 + col]     = o0;
            *(float2*)&g_head[((bh << 10) + q0 + row0 + 8) * 64 + col] = o1;
        }
    }
}

// ---------------- final: out = mean_h(head) @ Wh ------------------------------
__global__ void __launch_bounds__(256) out_kernel(const float* __restrict__ Wh,
                                                  float* __restrict__ out)
{
    extern __shared__ __align__(16) float sm2[];
    __shared__ float hm[8][64];
    int tid = threadIdx.x;
    int m0 = blockIdx.x * 8;
    int bb = m0 >> 10;
    int l0 = m0 & 1023;

    #pragma unroll
    for (int i = 0; i < 32; i++) {
        int e = tid + i * 256;
        ((float4*)sm2)[e] = ((const float4*)Wh)[e];
    }
    #pragma unroll
    for (int i = 0; i < 2; i++) {
        int e = tid + i * 256;
        int r = e >> 6, kk = e & 63;
        float s = 0.0f;
        #pragma unroll
        for (int hh = 0; hh < 8; hh++)
            s += g_head[(((size_t)(bb * H_ + hh) << 10) + l0 + r) * 64 + kk];
        hm[r][kk] = s * 0.125f;
    }
    __syncthreads();

    int ty = tid >> 6;
    int tx = tid & 63;
    float acc[2][8];
    #pragma unroll
    for (int i = 0; i < 2; i++)
        #pragma unroll
        for (int j = 0; j < 8; j++) acc[i][j] = 0.0f;
    #pragma unroll 8
    for (int d = 0; d < 64; d++) {
        float a0 = hm[ty * 2][d];
        float a1 = hm[ty * 2 + 1][d];
        float4 w0 = *(float4*)&sm2[d * 512 + tx * 8];
        float4 w1 = *(float4*)&sm2[d * 512 + tx * 8 + 4];
        acc[0][0] += a0 * w0.x; acc[0][1] += a0 * w0.y; acc[0][2] += a0 * w0.z; acc[0][3] += a0 * w0.w;
        acc[0][4] += a0 * w1.x; acc[0][5] += a0 * w1.y; acc[0][6] += a0 * w1.z; acc[0][7] += a0 * w1.w;
        acc[1][0] += a1 * w0.x; acc[1][1] += a1 * w0.y; acc[1][2] += a1 * w0.z; acc[1][3] += a1 * w0.w;
        acc[1][4] += a1 * w1.x; acc[1][5] += a1 * w1.y; acc[1][6] += a1 * w1.z; acc[1][7] += a1 * w1.w;
    }
    #pragma unroll
    for (int i = 0; i < 2; i++) {
        int m = m0 + ty * 2 + i;
        float4 o0 = {acc[i][0], acc[i][1], acc[i][2], acc[i][3]};
        float4 o1 = {acc[i][4], acc[i][5], acc[i][6], acc[i][7]};
        *(float4*)&out[(size_t)m * 512 + tx * 8]     = o0;
        *(float4*)&out[(size_t)m * 512 + tx * 8 + 4] = o1;
    }
}

// ---------------- launch ------------------------------------------------------
extern "C" void kernel_launch(void* const* d_in, const int* in_sizes, int n_in,
                              void* d_out, int out_size)
{
    const float* sat     = (const float*)d_in[0];
    const float* satpos  = (const float*)d_in[1];
    const float* ts      = (const float*)d_in[2];
    const float* tspos   = (const float*)d_in[3];
    const float* lsg     = (const float*)d_in[4];
    const float* lsb     = (const float*)d_in[5];
    const float* ltg     = (const float*)d_in[6];
    const float* ltb     = (const float*)d_in[7];
    const float* Wv      = (const float*)d_in[8];
    const float* bv      = (const float*)d_in[9];
    const float* Wq      = (const float*)d_in[10];
    const float* bq      = (const float*)d_in[11];
    const float* Wk      = (const float*)d_in[12];
    const float* bk      = (const float*)d_in[13];
    const float* Wsat    = (const float*)d_in[14];
    const float* bsat    = (const float*)d_in[15];
    const float* Wts     = (const float*)d_in[16];
    const float* bts     = (const float*)d_in[17];
    const float* Wh      = (const float*)d_in[18];

    float* out      = (float*)d_out;
    float* attn_out = out + OUT0_ELEMS;

    float *p_ss, *p_cs, *p_st, *p_ct, *p_v;
    __nv_bfloat16 *p_Ab, *p_As, *p_Wb, *p_Ws, *p_WVb, *p_WVs;
    __nv_bfloat16 *p_qb, *p_qs, *p_kb, *p_ks;
    cudaGetSymbolAddress((void**)&p_ss,  g_ss);
    cudaGetSymbolAddress((void**)&p_cs,  g_cs);
    cudaGetSymbolAddress((void**)&p_st,  g_st);
    cudaGetSymbolAddress((void**)&p_ct,  g_ct);
    cudaGetSymbolAddress((void**)&p_v,   g_v);
    cudaGetSymbolAddress((void**)&p_Ab,  g_Ab);
    cudaGetSymbolAddress((void**)&p_As,  g_As);
    cudaGetSymbolAddress((void**)&p_Wb,  g_Wb);
    cudaGetSymbolAddress((void**)&p_Ws,  g_Ws);
    cudaGetSymbolAddress((void**)&p_WVb, g_WVb);
    cudaGetSymbolAddress((void**)&p_WVs, g_WVs);
    cudaGetSymbolAddress((void**)&p_qb,  g_qb);
    cudaGetSymbolAddress((void**)&p_qs,  g_qs);
    cudaGetSymbolAddress((void**)&p_kb,  g_kb);
    cudaGetSymbolAddress((void**)&p_ks,  g_ks);

    cudaFuncSetAttribute(attn_kernel, cudaFuncAttributeMaxDynamicSharedMemorySize, ATTN_SMEM);
    cudaFuncSetAttribute(out_kernel,  cudaFuncAttributeMaxDynamicSharedMemorySize, 64 * 512 * 4);
    cudaFuncSetAttribute(gemm_bf16,   cudaFuncAttributeMaxDynamicSharedMemorySize, GEMM_SMEM);

    const size_t WSZ = (size_t)H_ * DK_ * D_;
    const size_t TE  = (size_t)TOK_ELEMS;

    // 1. LayerNorms
    ln_kernel<<<2 * M_ROWS, 128>>>(sat, ts, lsg, lsb, ltg, ltb);

    // 2. split pos embeddings
    split4_kernel<<<dim3(TOK_ELEMS / 1024, 4), 256>>>(satpos, satpos + TOK_ELEMS,
                                                      tspos, tspos + TOK_ELEMS);

    // 3. transpose + split weights
    transpose_w<<<dim3(8, 8), 256>>>(Wq,   p_Wb + 0 * WSZ, p_Ws + 0 * WSZ);
    transpose_w<<<dim3(8, 8), 256>>>(Wk,   p_Wb + 1 * WSZ, p_Ws + 1 * WSZ);
    transpose_w<<<dim3(8, 8), 256>>>(Wsat, p_Wb + 2 * WSZ, p_Ws + 2 * WSZ);
    transpose_w<<<dim3(8, 8), 256>>>(Wts,  p_Wb + 3 * WSZ, p_Ws + 3 * WSZ);
    transpose_w<<<dim3(1, 8), 256>>>(Wv,   p_WVb, p_WVs);

    // 4. sin/cos projections
    dim3 gg(M_ROWS / 128, 8);
    gemm_bf16<<<gg, 256, GEMM_SMEM>>>(p_Ab + 2 * TE, p_As + 2 * TE, p_Wb + 2 * WSZ, p_Ws + 2 * WSZ, bsat, p_ss, nullptr, nullptr, nullptr, nullptr, 0);
    gemm_bf16<<<gg, 256, GEMM_SMEM>>>(p_Ab + 3 * TE, p_As + 3 * TE, p_Wb + 2 * WSZ, p_Ws + 2 * WSZ, bsat, p_cs, nullptr, nullptr, nullptr, nullptr, 0);
    gemm_bf16<<<gg, 256, GEMM_SMEM>>>(p_Ab + 4 * TE, p_As + 4 * TE, p_Wb + 3 * WSZ, p_Ws + 3 * WSZ, bts,  p_st, nullptr, nullptr, nullptr, nullptr, 0);
    gemm_bf16<<<gg, 256, GEMM_SMEM>>>(p_Ab + 5 * TE, p_As + 5 * TE, p_Wb + 3 * WSZ, p_Ws + 3 * WSZ, bts,  p_ct, nullptr, nullptr, nullptr, nullptr, 0);

    // 5. q/k projections with fused RoPE epilogue -> split bf16
    gemm_bf16<<<gg, 256, GEMM_SMEM>>>(p_Ab + 1 * TE, p_As + 1 * TE, p_Wb + 0 * WSZ, p_Ws + 0 * WSZ, bq, nullptr, p_ct, p_st, p_qb, p_qs, 2);
    gemm_bf16<<<gg, 256, GEMM_SMEM>>>(p_Ab + 0 * TE, p_As + 0 * TE, p_Wb + 1 * WSZ, p_Ws + 1 * WSZ, bk, nullptr, p_cs, p_ss, p_kb, p_ks, 2);

    // 6. V projection + packed V^T operands
    gemm_bf16<<<dim3(M_ROWS / 128, 1), 256, GEMM_SMEM>>>(p_Ab + 0 * TE, p_As + 0 * TE, p_WVb, p_WVs, bv, p_v, nullptr, nullptr, nullptr, nullptr, 1);
    vprep_kernel<<<dim3(B_, 16), 256>>>();

    // 7. attention (pipelined)
    dim3 ga(L_ / QT, H_, B_);
    attn_kernel<<<ga, 256, ATTN_SMEM>>>(attn_out);

    // 8. out = mean_h(head) @ Wh
    out_kernel<<<M_ROWS / 8, 256, 64 * 512 * 4>>>(Wh, out);
}

// round 15
// speedup vs baseline: 1.4299x; 1.4299x over previous
#include <cuda_runtime.h>
#include <cuda_bf16.h>
#include <cstdint>

// Problem constants
#define B_   16
#define L_   1024
#define D_   512
#define H_   8
#define DK_  64
#define M_ROWS   (B_ * L_)            // 16384
#define TOK_ELEMS  (B_ * L_ * D_)     // 8388608
#define PROJ_ELEMS (B_ * H_ * L_ * DK_) // 8388608
#define OUT0_ELEMS ((size_t)B_ * L_ * D_)

// ---------------- scratch (device globals) ------------------------------------
__device__ __nv_bfloat16 g_Ab[6][TOK_ELEMS];
__device__ __nv_bfloat16 g_As[6][TOK_ELEMS];
__device__ __nv_bfloat16 g_Wb[4][H_ * DK_ * D_];
__device__ __nv_bfloat16 g_Ws[4][H_ * DK_ * D_];
__device__ __nv_bfloat16 g_WVb[DK_ * D_];
__device__ __nv_bfloat16 g_WVs[DK_ * D_];

__device__ float g_ss[PROJ_ELEMS];
__device__ float g_cs[PROJ_ELEMS];
__device__ float g_st[PROJ_ELEMS];
__device__ float g_ct[PROJ_ELEMS];
__device__ float g_head[PROJ_ELEMS];
__device__ __nv_bfloat16 g_qb[PROJ_ELEMS];
__device__ __nv_bfloat16 g_qs[PROJ_ELEMS];
__device__ __nv_bfloat16 g_kb[PROJ_ELEMS];
__device__ __nv_bfloat16 g_ks[PROJ_ELEMS];
// V^T packed operands: per (b,d) row of 1024 uint32; Vdup=(vb,vb), Vcmp=(vs,0)
__device__ uint32_t g_vd[B_ * DK_ * L_];
__device__ uint32_t g_vc[B_ * DK_ * L_];

// ---------------- PTX helpers --------------------------------------------------
__device__ __forceinline__ uint32_t smem_u32(const void* p) {
    uint32_t a;
    asm("{ .reg .u64 t; cvta.to.shared.u64 t, %1; cvt.u32.u64 %0, t; }" : "=r"(a) : "l"(p));
    return a;
}
#define CP_ASYNC16(dst, src) \
    asm volatile("cp.async.cg.shared.global [%0], [%1], 16;" :: "r"(dst), "l"(src) : "memory")
#define CP_COMMIT() asm volatile("cp.async.commit_group;" ::: "memory")
#define CP_WAIT0()  asm volatile("cp.async.wait_group 0;" ::: "memory")
#define CP_WAIT1()  asm volatile("cp.async.wait_group 1;" ::: "memory")

#define LDSM_X4(r0, r1, r2, r3, addr) \
    asm volatile("ldmatrix.sync.aligned.m8n8.x4.shared.b16 {%0,%1,%2,%3}, [%4];" \
        : "=r"(r0), "=r"(r1), "=r"(r2), "=r"(r3) : "r"(addr))

#define MMA_BF16(c, a0, a1, a2, a3, b0, b1) \
    asm volatile("mma.sync.aligned.m16n8k16.row.col.f32.bf16.bf16.f32 " \
        "{%0,%1,%2,%3},{%4,%5,%6,%7},{%8,%9},{%0,%1,%2,%3};" \
        : "+f"((c)[0]), "+f"((c)[1]), "+f"((c)[2]), "+f"((c)[3]) \
        : "r"(a0), "r"(a1), "r"(a2), "r"(a3), "r"(b0), "r"(b1))

__device__ __forceinline__ void bf16_split(float x, __nv_bfloat16& big, __nv_bfloat16& sml) {
    big = __float2bfloat16_rn(x);
    sml = __float2bfloat16_rn(x - __bfloat162float(big));
}
__device__ __forceinline__ uint16_t bf_bits(__nv_bfloat16 v) {
    uint16_t u; *(__nv_bfloat16*)&u = v; return u;
}
__device__ __forceinline__ uint32_t bf_pack(__nv_bfloat16 lo, __nv_bfloat16 hi) {
    return (uint32_t)bf_bits(lo) | ((uint32_t)bf_bits(hi) << 16);
}

// ---------------- LayerNorm (emits split bf16) ---------------------------------
__global__ void ln_kernel(const float* __restrict__ sat, const float* __restrict__ ts,
                          const float* __restrict__ gs, const float* __restrict__ bs,
                          const float* __restrict__ gt, const float* __restrict__ bt)
{
    int rid = blockIdx.x;
    const float* src; __nv_bfloat16 *db, *ds; const float* g; const float* bb;
    if (rid < M_ROWS) {
        src = sat + (size_t)rid * D_;
        db = g_Ab[0] + (size_t)rid * D_;  ds = g_As[0] + (size_t)rid * D_;
        g = gs; bb = bs;
    } else {
        int r = rid - M_ROWS;
        src = ts + (size_t)r * D_;
        db = g_Ab[1] + (size_t)r * D_;    ds = g_As[1] + (size_t)r * D_;
        g = gt; bb = bt;
    }
    int t = threadIdx.x;
    float4 x = ((const float4*)src)[t];
    float s  = x.x + x.y + x.z + x.w;
    float sq = x.x*x.x + x.y*x.y + x.z*x.z + x.w*x.w;
    #pragma unroll
    for (int o = 16; o; o >>= 1) {
        s  += __shfl_xor_sync(0xFFFFFFFFu, s,  o);
        sq += __shfl_xor_sync(0xFFFFFFFFu, sq, o);
    }
    __shared__ float ws[4], wq[4];
    if ((t & 31) == 0) { ws[t >> 5] = s; wq[t >> 5] = sq; }
    __syncthreads();
    s  = ws[0] + ws[1] + ws[2] + ws[3];
    sq = wq[0] + wq[1] + wq[2] + wq[3];
    float m   = s * (1.0f / D_);
    float var = sq * (1.0f / D_) - m * m;
    float inv = rsqrtf(var + 1e-5f);
    float4 g4 = ((const float4*)g)[t];
    float4 b4 = ((const float4*)bb)[t];
    float o[4];
    o[0] = (x.x - m) * inv * g4.x + b4.x;
    o[1] = (x.y - m) * inv * g4.y + b4.y;
    o[2] = (x.z - m) * inv * g4.z + b4.z;
    o[3] = (x.w - m) * inv * g4.w + b4.w;
    __nv_bfloat16 big[4], sml[4];
    #pragma unroll
    for (int i = 0; i < 4; i++) bf16_split(o[i], big[i], sml[i]);
    *(uint2*)&db[t * 4] = *(uint2*)big;
    *(uint2*)&ds[t * 4] = *(uint2*)sml;
}

// ---------------- merged split (all 4 pos-embedding tensors) -------------------
__global__ void split4_kernel(const float* __restrict__ x0, const float* __restrict__ x1,
                              const float* __restrict__ x2, const float* __restrict__ x3)
{
    int which = blockIdx.y;
    const float* x = (which == 0) ? x0 : (which == 1) ? x1 : (which == 2) ? x2 : x3;
    __nv_bfloat16* big = g_Ab[2 + which];
    __nv_bfloat16* sml = g_As[2 + which];
    int i = blockIdx.x * blockDim.x + threadIdx.x;
    float4 v = ((const float4*)x)[i];
    __nv_bfloat16 b[4], s[4];
    bf16_split(v.x, b[0], s[0]);
    bf16_split(v.y, b[1], s[1]);
    bf16_split(v.z, b[2], s[2]);
    bf16_split(v.w, b[3], s[3]);
    *(uint2*)&big[(size_t)i * 4] = *(uint2*)b;
    *(uint2*)&sml[(size_t)i * 4] = *(uint2*)s;
}

// ---------------- weight transpose + split -------------------------------------
__global__ void transpose_w(const float* __restrict__ W,
                            __nv_bfloat16* __restrict__ Wb, __nv_bfloat16* __restrict__ Wsml)
{
    __shared__ float t[64][65];
    int h = blockIdx.x, k0 = blockIdx.y * 64;
    const float* Wp = W + (size_t)h * (D_ * DK_);
    #pragma unroll
    for (int i = 0; i < 16; i++) {
        int e = threadIdx.x + i * 256;
        int r = e >> 6, c = e & 63;
        t[r][c] = Wp[(size_t)(k0 + r) * 64 + c];
    }
    __syncthreads();
    #pragma unroll
    for (int i = 0; i < 16; i++) {
        int e = threadIdx.x + i * 256;
        int n = e >> 6, kk = e & 63;
        __nv_bfloat16 big, sml;
        bf16_split(t[kk][n], big, sml);
        size_t off = (size_t)h * (DK_ * D_) + (size_t)n * 512 + k0 + kk;
        Wb[off] = big;
        Wsml[off] = sml;
    }
}

// ---------------- 3xBF16 projection GEMM (stride-144 packed rows) ---------------
// mode 0: fp32 head layout. mode 1: V -> packed V^T operands (g_vd/g_vc) directly.
// mode 2: RoPE epilogue -> split bf16 q/k.
#define GSTR 144
#define GA_SZ (128 * GSTR)
#define GB_SZ (64 * GSTR)
#define GSTG (GA_SZ + GB_SZ)
#define GEMM_SMEM (2 * GSTG)

__global__ void __launch_bounds__(256) gemm_bf16(const __nv_bfloat16* __restrict__ Ab,
                                                 const __nv_bfloat16* __restrict__ As,
                                                 const __nv_bfloat16* __restrict__ Bb,
                                                 const __nv_bfloat16* __restrict__ Bs,
                                                 const float* __restrict__ bias,
                                                 float* __restrict__ C,
                                                 const float* __restrict__ cosA,
                                                 const float* __restrict__ sinA,
                                                 __nv_bfloat16* __restrict__ outB,
                                                 __nv_bfloat16* __restrict__ outS,
                                                 int mode)
{
    extern __shared__ __align__(16) char smraw[];
    uint32_t sb = smem_u32(smraw);
    int tid = threadIdx.x, lane = tid & 31, wid = tid >> 5;
    int warp_m = wid >> 1, warp_n = wid & 1;
    int m0 = blockIdx.x * 128, by = blockIdx.y, n0 = by * 64;

    uint32_t laneA = (uint32_t)((warp_m * 32 + (lane & 7) + ((lane >> 3) & 1) * 8) * GSTR + (lane >> 4) * 16);
    uint32_t laneB = (uint32_t)((warp_n * 32 + (lane & 7) + ((lane >> 3) & 1) * 8) * GSTR + (lane >> 4) * 16);

    float c[8][4];
    #pragma unroll
    for (int i = 0; i < 8; i++)
        #pragma unroll
        for (int j = 0; j < 4; j++) c[i][j] = 0.0f;

    auto load_stage = [&](int s, int k0) {
        uint32_t base = sb + s * GSTG;
        #pragma unroll
        for (int i = 0; i < 4; i++) {
            int e = tid + i * 256, r = e >> 3, cc = e & 7;
            const __nv_bfloat16* src = (cc < 4)
                ? Ab + (size_t)(m0 + r) * 512 + k0 + cc * 8
                : As + (size_t)(m0 + r) * 512 + k0 + (cc - 4) * 8;
            CP_ASYNC16(base + (uint32_t)(r * GSTR + cc * 16), src);
        }
        #pragma unroll
        for (int i = 0; i < 2; i++) {
            int e = tid + i * 256, r = e >> 3, cc = e & 7;
            const __nv_bfloat16* src = (cc < 4)
                ? Bb + (size_t)(n0 + r) * 512 + k0 + cc * 8
                : Bs + (size_t)(n0 + r) * 512 + k0 + (cc - 4) * 8;
            CP_ASYNC16(base + GA_SZ + (uint32_t)(r * GSTR + cc * 16), src);
        }
    };

    auto compute = [&](int s) {
        uint32_t abase = sb + s * GSTG + laneA;
        uint32_t bbase = sb + s * GSTG + GA_SZ + laneB;
        #pragma unroll
        for (int ks = 0; ks < 2; ks++) {
            uint32_t aB[2][4], aS[2][4], bB[2][4], bS[2][4];
            #pragma unroll
            for (int mt = 0; mt < 2; mt++) {
                LDSM_X4(aB[mt][0], aB[mt][1], aB[mt][2], aB[mt][3], abase + mt * (16 * GSTR) + ks * 32);
                LDSM_X4(aS[mt][0], aS[mt][1], aS[mt][2], aS[mt][3], abase + mt * (16 * GSTR) + 64 + ks * 32);
            }
            #pragma unroll
            for (int nt = 0; nt < 2; nt++) {
                LDSM_X4(bB[nt][0], bB[nt][1], bB[nt][2], bB[nt][3], bbase + nt * (16 * GSTR) + ks * 32);
                LDSM_X4(bS[nt][0], bS[nt][1], bS[nt][2], bS[nt][3], bbase + nt * (16 * GSTR) + 64 + ks * 32);
            }
            #pragma unroll
            for (int mt = 0; mt < 2; mt++)
                #pragma unroll
                for (int j = 0; j < 4; j++) {
                    int nt = j >> 1, hh = j & 1;
                    float* cc = c[mt * 4 + j];
                    MMA_BF16(cc, aS[mt][0], aS[mt][1], aS[mt][2], aS[mt][3], bB[nt][hh], bB[nt][2 + hh]);
                    MMA_BF16(cc, aB[mt][0], aB[mt][1], aB[mt][2], aB[mt][3], bS[nt][hh], bS[nt][2 + hh]);
                    MMA_BF16(cc, aB[mt][0], aB[mt][1], aB[mt][2], aB[mt][3], bB[nt][hh], bB[nt][2 + hh]);
                }
        }
    };

    load_stage(0, 0);
    CP_COMMIT();
    for (int ck = 0; ck < 16; ck++) {
        if (ck < 15) {
            load_stage((ck + 1) & 1, (ck + 1) * 32);
            CP_COMMIT();
            CP_WAIT1();
        } else {
            CP_WAIT0();
        }
        __syncthreads();
        compute(ck & 1);
        __syncthreads();
    }

    int r_lane = lane >> 2, c_lane = (lane & 3) * 2;
    #pragma unroll
    for (int i = 0; i < 2; i++) {
        #pragma unroll
        for (int j = 0; j < 4; j++) {
            float* cc = c[i * 4 + j];
            int nc = warp_n * 32 + j * 8 + c_lane;           // even
            int mrow = m0 + warp_m * 32 + i * 16 + r_lane;
            if (mode == 1) {
                // V: split + pack + transpose directly into g_vd / g_vc
                float2 bb2 = *(const float2*)&bias[nc];
                #pragma unroll
                for (int rr2 = 0; rr2 < 2; rr2++) {
                    int row = mrow + rr2 * 8;
                    int bi = row >> 10, li = row & 1023;
                    float v0 = cc[rr2 * 2]     + bb2.x;
                    float v1 = cc[rr2 * 2 + 1] + bb2.y;
                    __nv_bfloat16 vb, vs;
                    bf16_split(v0, vb, vs);
                    size_t o0 = (((size_t)bi * DK_) + nc) * L_ + li;
                    uint32_t ub = bf_bits(vb);
                    g_vd[o0] = ub | (ub << 16);
                    g_vc[o0] = bf_bits(vs);
                    bf16_split(v1, vb, vs);
                    size_t o1 = (((size_t)bi * DK_) + nc + 1) * L_ + li;
                    ub = bf_bits(vb);
                    g_vd[o1] = ub | (ub << 16);
                    g_vc[o1] = bf_bits(vs);
                }
                continue;
            }
            float2 bb2 = *(const float2*)&bias[by * 64 + nc];
            int b0r = mrow >> 10, l0r = mrow & 1023;
            int b1r = (mrow + 8) >> 10, l1r = (mrow + 8) & 1023;
            size_t base0 = ((((size_t)(b0r * 8 + by)) << 10) + l0r) * 64 + nc;
            size_t base1 = ((((size_t)(b1r * 8 + by)) << 10) + l1r) * 64 + nc;
            float v00 = cc[0] + bb2.x, v01 = cc[1] + bb2.y;
            float v10 = cc[2] + bb2.x, v11 = cc[3] + bb2.y;
            if (mode == 2) {
                float2 cv0 = *(const float2*)&cosA[base0];
                float2 sv0 = *(const float2*)&sinA[base0];
                float2 cv1 = *(const float2*)&cosA[base1];
                float2 sv1 = *(const float2*)&sinA[base1];
                float o00 = v00 * cv0.x - v01 * sv0.x;
                float o01 = v01 * cv0.y + v00 * sv0.y;
                float o10 = v10 * cv1.x - v11 * sv1.x;
                float o11 = v11 * cv1.y + v10 * sv1.y;
                __nv_bfloat16 b0, s0, b1, s1;
                bf16_split(o00, b0, s0); bf16_split(o01, b1, s1);
                *(uint32_t*)&outB[base0] = bf_pack(b0, b1);
                *(uint32_t*)&outS[base0] = bf_pack(s0, s1);
                bf16_split(o10, b0, s0); bf16_split(o11, b1, s1);
                *(uint32_t*)&outB[base1] = bf_pack(b0, b1);
                *(uint32_t*)&outS[base1] = bf_pack(s0, s1);
            } else {
                float2 o0 = {v00, v01};
                float2 o1 = {v10, v11};
                *(float2*)&C[base0] = o0;
                *(float2*)&C[base1] = o1;
            }
        }
    }
}

// ---------------- attention: bf16x3 QK^T + packed-bf16 MMA PV (R13, proven) -----
#define QT  32
#define KT  256
#define SCP 1028
#define STRK 144
#define STRV 528
#define SC_BYTES   (QT * SCP * 4)
#define KREG_OFF   SC_BYTES
#define KREG_BYTES (2 * KT * STRK)
#define VC_OFF     (64 * STRV)
#define QREG_OFF   (KREG_OFF + KREG_BYTES)
#define QB_BYTES   (QT * STRK)
#define ATTN_SMEM  (QREG_OFF + 2 * QB_BYTES)

__global__ void __launch_bounds__(256) attn_kernel(float* __restrict__ attn_out)
{
    extern __shared__ __align__(16) float smf[];
    float* sc  = smf;
    uint32_t* scu = (uint32_t*)smf;
    char*  kreg = (char*)smf + KREG_OFF;
    char*  qreg = (char*)smf + QREG_OFF;

    int tid = threadIdx.x, lane = tid & 31, wid = tid >> 5;
    int q0 = blockIdx.x * QT;
    int h  = blockIdx.y;
    int b  = blockIdx.z;
    size_t bh = (size_t)(b * H_ + h);

    uint32_t skb = smem_u32(kreg), sqb = smem_u32(qreg), ssb = smem_u32(sc);

    {
        int r = tid >> 3, cch = tid & 7;
        const uint4* srcb = (const uint4*)&g_qb[((bh << 10) + q0 + r) * 64];
        const uint4* srcs = (const uint4*)&g_qs[((bh << 10) + q0 + r) * 64];
        *(uint4*)(qreg + r * STRK + cch * 16)            = srcb[cch];
        *(uint4*)(qreg + QB_BYTES + r * STRK + cch * 16) = srcs[cch];
    }

    uint32_t aB0 = sqb + (uint32_t)(((lane & 7) + ((lane >> 3) & 1) * 8) * STRK + (lane >> 4) * 16);
    uint32_t aS0 = aB0 + QB_BYTES;
    uint32_t bB0 = skb + (uint32_t)((wid * 32 + (lane & 7) + ((lane >> 3) & 1) * 8) * STRK + (lane >> 4) * 16);
    uint32_t bS0 = bB0 + (uint32_t)(KT * STRK);

    for (int kt = 0; kt < 4; kt++) {
        __syncthreads();
        size_t kbase = ((bh << 10) + kt * KT) * 64;
        #pragma unroll
        for (int i = 0; i < 8; i++) {
            int e = tid + i * 256, r = e >> 3, cch = e & 7;
            const uint4* srcb = (const uint4*)&g_kb[kbase + (size_t)r * 64];
            const uint4* srcs = (const uint4*)&g_ks[kbase + (size_t)r * 64];
            *(uint4*)(kreg + r * STRK + cch * 16)             = srcb[cch];
            *(uint4*)(kreg + KT * STRK + r * STRK + cch * 16) = srcs[cch];
        }
        __syncthreads();

        float c[2][4][4];
        #pragma unroll
        for (int mt = 0; mt < 2; mt++)
            #pragma unroll
            for (int j = 0; j < 4; j++)
                #pragma unroll
                for (int e = 0; e < 4; e++) c[mt][j][e] = 0.0f;

        #pragma unroll
        for (int ks = 0; ks < 4; ks++) {
            uint32_t aB[2][4], aS[2][4], bB[2][4], bS[2][4];
            #pragma unroll
            for (int mt = 0; mt < 2; mt++) {
                LDSM_X4(aB[mt][0], aB[mt][1], aB[mt][2], aB[mt][3], aB0 + mt * (16 * STRK) + ks * 32);
                LDSM_X4(aS[mt][0], aS[mt][1], aS[mt][2], aS[mt][3], aS0 + mt * (16 * STRK) + ks * 32);
            }
            #pragma unroll
            for (int nt = 0; nt < 2; nt++) {
                LDSM_X4(bB[nt][0], bB[nt][1], bB[nt][2], bB[nt][3], bB0 + nt * (16 * STRK) + ks * 32);
                LDSM_X4(bS[nt][0], bS[nt][1], bS[nt][2], bS[nt][3], bS0 + nt * (16 * STRK) + ks * 32);
            }
            #pragma unroll
            for (int mt = 0; mt < 2; mt++)
                #pragma unroll
                for (int j = 0; j < 4; j++) {
                    int nt = j >> 1, hh = j & 1;
                    float* cc = c[mt][j];
                    MMA_BF16(cc, aS[mt][0], aS[mt][1], aS[mt][2], aS[mt][3], bB[nt][hh], bB[nt][2 + hh]);
                    MMA_BF16(cc, aB[mt][0], aB[mt][1], aB[mt][2], aB[mt][3], bS[nt][hh], bS[nt][2 + hh]);
                    MMA_BF16(cc, aB[mt][0], aB[mt][1], aB[mt][2], aB[mt][3], bB[nt][hh], bB[nt][2 + hh]);
                }
        }
        int rr = lane >> 2, ccl = (lane & 3) * 2;
        #pragma unroll
        for (int mt = 0; mt < 2; mt++)
            #pragma unroll
            for (int j = 0; j < 4; j++) {
                int col = kt * KT + wid * 32 + j * 8 + ccl;
                int row0 = mt * 16 + rr;
                float2 o0 = {c[mt][j][0] * 0.125f, c[mt][j][1] * 0.125f};
                float2 o1 = {c[mt][j][2] * 0.125f, c[mt][j][3] * 0.125f};
                *(float2*)&sc[row0 * SCP + col]       = o0;
                *(float2*)&sc[(row0 + 8) * SCP + col] = o1;
            }
    }
    __syncthreads();

    for (int rr = wid * 4; rr < wid * 4 + 4; rr++) {
        float vals[32];
        float mx = -1e30f;
        #pragma unroll
        for (int j = 0; j < 32; j++) {
            vals[j] = sc[rr * SCP + lane + 32 * j];
            mx = fmaxf(mx, vals[j]);
        }
        #pragma unroll
        for (int o = 16; o; o >>= 1) mx = fmaxf(mx, __shfl_xor_sync(0xFFFFFFFFu, mx, o));
        float s = 0.0f;
        #pragma unroll
        for (int j = 0; j < 32; j++) { vals[j] = __expf(vals[j] - mx); s += vals[j]; }
        #pragma unroll
        for (int o = 16; o; o >>= 1) s += __shfl_xor_sync(0xFFFFFFFFu, s, o);
        float inv = 1.0f / s;
        size_t obase = (((size_t)(b * L_ + q0 + rr) * H_ + h) << 10);
        #pragma unroll
        for (int j = 0; j < 32; j++) {
            float p = vals[j] * inv;
            attn_out[obase + lane + 32 * j] = p;
            __nv_bfloat16 pb, ps;
            bf16_split(p, pb, ps);
            scu[rr * SCP + lane + 32 * j] = bf_pack(pb, ps);
        }
    }

    int mt = wid >> 2, nt = wid & 3;
    float acc[2][4];
    #pragma unroll
    for (int j = 0; j < 2; j++)
        #pragma unroll
        for (int e = 0; e < 4; e++) acc[j][e] = 0.0f;

    uint32_t aP0 = ssb + (uint32_t)((mt * 16 + (lane & 7) + ((lane >> 3) & 1) * 8) * (SCP * 4) + (lane >> 4) * 16);
    uint32_t vD0 = skb + (uint32_t)((nt * 16 + (lane & 7) + ((lane >> 3) & 1) * 8) * STRV + (lane >> 4) * 16);
    uint32_t vC0 = vD0 + (uint32_t)VC_OFF;

    for (int vt = 0; vt < 8; vt++) {
        __syncthreads();
        {
            const uint32_t* vdg = g_vd + ((size_t)b * DK_) * L_ + vt * 128;
            const uint32_t* vcg = g_vc + ((size_t)b * DK_) * L_ + vt * 128;
            #pragma unroll
            for (int i = 0; i < 8; i++) {
                int e = tid + i * 256, r = e >> 5, ch = e & 31;
                *(uint4*)(kreg + r * STRV + ch * 16)          = *(const uint4*)(vdg + (size_t)r * L_ + ch * 4);
                *(uint4*)(kreg + VC_OFF + r * STRV + ch * 16) = *(const uint4*)(vcg + (size_t)r * L_ + ch * 4);
            }
        }
        __syncthreads();
        #pragma unroll
        for (int st = 0; st < 16; st++) {
            uint32_t a[4], bd[4], bc[4];
            LDSM_X4(a[0], a[1], a[2], a[3], aP0 + (uint32_t)(vt * 512 + st * 32));
            LDSM_X4(bd[0], bd[1], bd[2], bd[3], vD0 + st * 32);
            LDSM_X4(bc[0], bc[1], bc[2], bc[3], vC0 + st * 32);
            #pragma unroll
            for (int j = 0; j < 2; j++) {
                MMA_BF16(acc[j], a[0], a[1], a[2], a[3], bd[j], bd[2 + j]);
                MMA_BF16(acc[j], a[0], a[1], a[2], a[3], bc[j], bc[2 + j]);
            }
        }
    }
    {
        int rr = lane >> 2, cl = (lane & 3) * 2;
        #pragma unroll
        for (int j = 0; j < 2; j++) {
            int col = nt * 16 + j * 8 + cl;
            int row0 = mt * 16 + rr;
            float2 o0 = {acc[j][0], acc[j][1]};
            float2 o1 = {acc[j][2], acc[j][3]};
            *(float2*)&g_head[((bh << 10) + q0 + row0) * 64 + col]     = o0;
            *(float2*)&g_head[((bh << 10) + q0 + row0 + 8) * 64 + col] = o1;
        }
    }
}

// ---------------- final: out = mean_h(head) @ Wh ------------------------------
__global__ void __launch_bounds__(256) out_kernel(const float* __restrict__ Wh,
                                                  float* __restrict__ out)
{
    extern __shared__ __align__(16) float sm2[];
    __shared__ float hm[8][64];
    int tid = threadIdx.x;
    int m0 = blockIdx.x * 8;
    int bb = m0 >> 10;
    int l0 = m0 & 1023;

    #pragma unroll
    for (int i = 0; i < 32; i++) {
        int e = tid + i * 256;
        ((float4*)sm2)[e] = ((const float4*)Wh)[e];
    }
    #pragma unroll
    for (int i = 0; i < 2; i++) {
        int e = tid + i * 256;
        int r = e >> 6, kk = e & 63;
        float s = 0.0f;
        #pragma unroll
        for (int hh = 0; hh < 8; hh++)
            s += g_head[(((size_t)(bb * H_ + hh) << 10) + l0 + r) * 64 + kk];
        hm[r][kk] = s * 0.125f;
    }
    __syncthreads();

    int ty = tid >> 6;
    int tx = tid & 63;
    float acc[2][8];
    #pragma unroll
    for (int i = 0; i < 2; i++)
        #pragma unroll
        for (int j = 0; j < 8; j++) acc[i][j] = 0.0f;
    #pragma unroll 8
    for (int d = 0; d < 64; d++) {
        float a0 = hm[ty * 2][d];
        float a1 = hm[ty * 2 + 1][d];
        float4 w0 = *(float4*)&sm2[d * 512 + tx * 8];
        float4 w1 = *(float4*)&sm2[d * 512 + tx * 8 + 4];
        acc[0][0] += a0 * w0.x; acc[0][1] += a0 * w0.y; acc[0][2] += a0 * w0.z; acc[0][3] += a0 * w0.w;
        acc[0][4] += a0 * w1.x; acc[0][5] += a0 * w1.y; acc[0][6] += a0 * w1.z; acc[0][7] += a0 * w1.w;
        acc[1][0] += a1 * w0.x; acc[1][1] += a1 * w0.y; acc[1][2] += a1 * w0.z; acc[1][3] += a1 * w0.w;
        acc[1][4] += a1 * w1.x; acc[1][5] += a1 * w1.y; acc[1][6] += a1 * w1.z; acc[1][7] += a1 * w1.w;
    }
    #pragma unroll
    for (int i = 0; i < 2; i++) {
        int m = m0 + ty * 2 + i;
        float4 o0 = {acc[i][0], acc[i][1], acc[i][2], acc[i][3]};
        float4 o1 = {acc[i][4], acc[i][5], acc[i][6], acc[i][7]};
        *(float4*)&out[(size_t)m * 512 + tx * 8]     = o0;
        *(float4*)&out[(size_t)m * 512 + tx * 8 + 4] = o1;
    }
}

// ---------------- launch ------------------------------------------------------
extern "C" void kernel_launch(void* const* d_in, const int* in_sizes, int n_in,
                              void* d_out, int out_size)
{
    const float* sat     = (const float*)d_in[0];
    const float* satpos  = (const float*)d_in[1];
    const float* ts      = (const float*)d_in[2];
    const float* tspos   = (const float*)d_in[3];
    const float* lsg     = (const float*)d_in[4];
    const float* lsb     = (const float*)d_in[5];
    const float* ltg     = (const float*)d_in[6];
    const float* ltb     = (const float*)d_in[7];
    const float* Wv      = (const float*)d_in[8];
    const float* bv      = (const float*)d_in[9];
    const float* Wq      = (const float*)d_in[10];
    const float* bq      = (const float*)d_in[11];
    const float* Wk      = (const float*)d_in[12];
    const float* bk      = (const float*)d_in[13];
    const float* Wsat    = (const float*)d_in[14];
    const float* bsat    = (const float*)d_in[15];
    const float* Wts     = (const float*)d_in[16];
    const float* bts     = (const float*)d_in[17];
    const float* Wh      = (const float*)d_in[18];

    float* out      = (float*)d_out;
    float* attn_out = out + OUT0_ELEMS;

    float *p_ss, *p_cs, *p_st, *p_ct;
    __nv_bfloat16 *p_Ab, *p_As, *p_Wb, *p_Ws, *p_WVb, *p_WVs;
    __nv_bfloat16 *p_qb, *p_qs, *p_kb, *p_ks;
    cudaGetSymbolAddress((void**)&p_ss,  g_ss);
    cudaGetSymbolAddress((void**)&p_cs,  g_cs);
    cudaGetSymbolAddress((void**)&p_st,  g_st);
    cudaGetSymbolAddress((void**)&p_ct,  g_ct);
    cudaGetSymbolAddress((void**)&p_Ab,  g_Ab);
    cudaGetSymbolAddress((void**)&p_As,  g_As);
    cudaGetSymbolAddress((void**)&p_Wb,  g_Wb);
    cudaGetSymbolAddress((void**)&p_Ws,  g_Ws);
    cudaGetSymbolAddress((void**)&p_WVb, g_WVb);
    cudaGetSymbolAddress((void**)&p_WVs, g_WVs);
    cudaGetSymbolAddress((void**)&p_qb,  g_qb);
    cudaGetSymbolAddress((void**)&p_qs,  g_qs);
    cudaGetSymbolAddress((void**)&p_kb,  g_kb);
    cudaGetSymbolAddress((void**)&p_ks,  g_ks);

    cudaFuncSetAttribute(attn_kernel, cudaFuncAttributeMaxDynamicSharedMemorySize, ATTN_SMEM);
    cudaFuncSetAttribute(out_kernel,  cudaFuncAttributeMaxDynamicSharedMemorySize, 64 * 512 * 4);
    cudaFuncSetAttribute(gemm_bf16,   cudaFuncAttributeMaxDynamicSharedMemorySize, GEMM_SMEM);

    const size_t WSZ = (size_t)H_ * DK_ * D_;
    const size_t TE  = (size_t)TOK_ELEMS;

    // 1. LayerNorms
    ln_kernel<<<2 * M_ROWS, 128>>>(sat, ts, lsg, lsb, ltg, ltb);

    // 2. split pos embeddings
    split4_kernel<<<dim3(TOK_ELEMS / 1024, 4), 256>>>(satpos, satpos + TOK_ELEMS,
                                                      tspos, tspos + TOK_ELEMS);

    // 3. transpose + split weights
    transpose_w<<<dim3(8, 8), 256>>>(Wq,   p_Wb + 0 * WSZ, p_Ws + 0 * WSZ);
    transpose_w<<<dim3(8, 8), 256>>>(Wk,   p_Wb + 1 * WSZ, p_Ws + 1 * WSZ);
    transpose_w<<<dim3(8, 8), 256>>>(Wsat, p_Wb + 2 * WSZ, p_Ws + 2 * WSZ);
    transpose_w<<<dim3(8, 8), 256>>>(Wts,  p_Wb + 3 * WSZ, p_Ws + 3 * WSZ);
    transpose_w<<<dim3(1, 8), 256>>>(Wv,   p_WVb, p_WVs);

    // 4. sin/cos projections
    dim3 gg(M_ROWS / 128, 8);
    gemm_bf16<<<gg, 256, GEMM_SMEM>>>(p_Ab + 2 * TE, p_As + 2 * TE, p_Wb + 2 * WSZ, p_Ws + 2 * WSZ, bsat, p_ss, nullptr, nullptr, nullptr, nullptr, 0);
    gemm_bf16<<<gg, 256, GEMM_SMEM>>>(p_Ab + 3 * TE, p_As + 3 * TE, p_Wb + 2 * WSZ, p_Ws + 2 * WSZ, bsat, p_cs, nullptr, nullptr, nullptr, nullptr, 0);
    gemm_bf16<<<gg, 256, GEMM_SMEM>>>(p_Ab + 4 * TE, p_As + 4 * TE, p_Wb + 3 * WSZ, p_Ws + 3 * WSZ, bts,  p_st, nullptr, nullptr, nullptr, nullptr, 0);
    gemm_bf16<<<gg, 256, GEMM_SMEM>>>(p_Ab + 5 * TE, p_As + 5 * TE, p_Wb + 3 * WSZ, p_Ws + 3 * WSZ, bts,  p_ct, nullptr, nullptr, nullptr, nullptr, 0);

    // 5. q/k projections with fused RoPE epilogue -> split bf16
    gemm_bf16<<<gg, 256, GEMM_SMEM>>>(p_Ab + 1 * TE, p_As + 1 * TE, p_Wb + 0 * WSZ, p_Ws + 0 * WSZ, bq, nullptr, p_ct, p_st, p_qb, p_qs, 2);
    gemm_bf16<<<gg, 256, GEMM_SMEM>>>(p_Ab + 0 * TE, p_As + 0 * TE, p_Wb + 1 * WSZ, p_Ws + 1 * WSZ, bk, nullptr, p_cs, p_ss, p_kb, p_ks, 2);

    // 6. V projection with fused split/pack/transpose epilogue (replaces vprep)
    gemm_bf16<<<dim3(M_ROWS / 128, 1), 256, GEMM_SMEM>>>(p_Ab + 0 * TE, p_As + 0 * TE, p_WVb, p_WVs, bv, nullptr, nullptr, nullptr, nullptr, nullptr, 1);

    // 7. attention (R13 config, proven)
    dim3 ga(L_ / QT, H_, B_);
    attn_kernel<<<ga, 256, ATTN_SMEM>>>(attn_out);

    // 8. out = mean_h(head) @ Wh
    out_kernel<<<M_ROWS / 8, 256, 64 * 512 * 4>>>(Wh, out);
}

// round 16
// speedup vs baseline: 1.4885x; 1.0409x over previous
#include <cuda_runtime.h>
#include <cuda_bf16.h>
#include <cstdint>

// Problem constants
#define B_   16
#define L_   1024
#define D_   512
#define H_   8
#define DK_  64
#define M_ROWS   (B_ * L_)            // 16384
#define TOK_ELEMS  (B_ * L_ * D_)     // 8388608
#define PROJ_ELEMS (B_ * H_ * L_ * DK_) // 8388608
#define OUT0_ELEMS ((size_t)B_ * L_ * D_)

// ---------------- scratch (device globals) ------------------------------------
__device__ __nv_bfloat16 g_Ab[6][TOK_ELEMS];
__device__ __nv_bfloat16 g_As[6][TOK_ELEMS];
__device__ __nv_bfloat16 g_Wb[4][H_ * DK_ * D_];
__device__ __nv_bfloat16 g_Ws[4][H_ * DK_ * D_];
__device__ __nv_bfloat16 g_WVb[DK_ * D_];
__device__ __nv_bfloat16 g_WVs[DK_ * D_];

__device__ float g_ss[PROJ_ELEMS];
__device__ float g_cs[PROJ_ELEMS];
__device__ float g_st[PROJ_ELEMS];
__device__ float g_ct[PROJ_ELEMS];
__device__ float g_head[PROJ_ELEMS];
__device__ __nv_bfloat16 g_qb[PROJ_ELEMS];
__device__ __nv_bfloat16 g_qs[PROJ_ELEMS];
__device__ __nv_bfloat16 g_kb[PROJ_ELEMS];
__device__ __nv_bfloat16 g_ks[PROJ_ELEMS];
__device__ uint32_t g_vd[B_ * DK_ * L_];
__device__ uint32_t g_vc[B_ * DK_ * L_];

// ---------------- PTX helpers --------------------------------------------------
__device__ __forceinline__ uint32_t smem_u32(const void* p) {
    uint32_t a;
    asm("{ .reg .u64 t; cvta.to.shared.u64 t, %1; cvt.u32.u64 %0, t; }" : "=r"(a) : "l"(p));
    return a;
}
#define CP_ASYNC16(dst, src) \
    asm volatile("cp.async.cg.shared.global [%0], [%1], 16;" :: "r"(dst), "l"(src) : "memory")
#define CP_COMMIT() asm volatile("cp.async.commit_group;" ::: "memory")
#define CP_WAIT0()  asm volatile("cp.async.wait_group 0;" ::: "memory")
#define CP_WAIT1()  asm volatile("cp.async.wait_group 1;" ::: "memory")

#define LDSM_X4(r0, r1, r2, r3, addr) \
    asm volatile("ldmatrix.sync.aligned.m8n8.x4.shared.b16 {%0,%1,%2,%3}, [%4];" \
        : "=r"(r0), "=r"(r1), "=r"(r2), "=r"(r3) : "r"(addr))

#define MMA_BF16(c, a0, a1, a2, a3, b0, b1) \
    asm volatile("mma.sync.aligned.m16n8k16.row.col.f32.bf16.bf16.f32 " \
        "{%0,%1,%2,%3},{%4,%5,%6,%7},{%8,%9},{%0,%1,%2,%3};" \
        : "+f"((c)[0]), "+f"((c)[1]), "+f"((c)[2]), "+f"((c)[3]) \
        : "r"(a0), "r"(a1), "r"(a2), "r"(a3), "r"(b0), "r"(b1))

__device__ __forceinline__ void bf16_split(float x, __nv_bfloat16& big, __nv_bfloat16& sml) {
    big = __float2bfloat16_rn(x);
    sml = __float2bfloat16_rn(x - __bfloat162float(big));
}
__device__ __forceinline__ uint16_t bf_bits(__nv_bfloat16 v) {
    uint16_t u; *(__nv_bfloat16*)&u = v; return u;
}
__device__ __forceinline__ uint32_t bf_pack(__nv_bfloat16 lo, __nv_bfloat16 hi) {
    return (uint32_t)bf_bits(lo) | ((uint32_t)bf_bits(hi) << 16);
}

// ---------------- LayerNorm (emits split bf16) ---------------------------------
__global__ void ln_kernel(const float* __restrict__ sat, const float* __restrict__ ts,
                          const float* __restrict__ gs, const float* __restrict__ bs,
                          const float* __restrict__ gt, const float* __restrict__ bt)
{
    int rid = blockIdx.x;
    const float* src; __nv_bfloat16 *db, *ds; const float* g; const float* bb;
    if (rid < M_ROWS) {
        src = sat + (size_t)rid * D_;
        db = g_Ab[0] + (size_t)rid * D_;  ds = g_As[0] + (size_t)rid * D_;
        g = gs; bb = bs;
    } else {
        int r = rid - M_ROWS;
        src = ts + (size_t)r * D_;
        db = g_Ab[1] + (size_t)r * D_;    ds = g_As[1] + (size_t)r * D_;
        g = gt; bb = bt;
    }
    int t = threadIdx.x;
    float4 x = ((const float4*)src)[t];
    float s  = x.x + x.y + x.z + x.w;
    float sq = x.x*x.x + x.y*x.y + x.z*x.z + x.w*x.w;
    #pragma unroll
    for (int o = 16; o; o >>= 1) {
        s  += __shfl_xor_sync(0xFFFFFFFFu, s,  o);
        sq += __shfl_xor_sync(0xFFFFFFFFu, sq, o);
    }
    __shared__ float ws[4], wq[4];
    if ((t & 31) == 0) { ws[t >> 5] = s; wq[t >> 5] = sq; }
    __syncthreads();
    s  = ws[0] + ws[1] + ws[2] + ws[3];
    sq = wq[0] + wq[1] + wq[2] + wq[3];
    float m   = s * (1.0f / D_);
    float var = sq * (1.0f / D_) - m * m;
    float inv = rsqrtf(var + 1e-5f);
    float4 g4 = ((const float4*)g)[t];
    float4 b4 = ((const float4*)bb)[t];
    float o[4];
    o[0] = (x.x - m) * inv * g4.x + b4.x;
    o[1] = (x.y - m) * inv * g4.y + b4.y;
    o[2] = (x.z - m) * inv * g4.z + b4.z;
    o[3] = (x.w - m) * inv * g4.w + b4.w;
    __nv_bfloat16 big[4], sml[4];
    #pragma unroll
    for (int i = 0; i < 4; i++) bf16_split(o[i], big[i], sml[i]);
    *(uint2*)&db[t * 4] = *(uint2*)big;
    *(uint2*)&ds[t * 4] = *(uint2*)sml;
}

// ---------------- merged split (all 4 pos-embedding tensors) -------------------
__global__ void split4_kernel(const float* __restrict__ x0, const float* __restrict__ x1,
                              const float* __restrict__ x2, const float* __restrict__ x3)
{
    int which = blockIdx.y;
    const float* x = (which == 0) ? x0 : (which == 1) ? x1 : (which == 2) ? x2 : x3;
    __nv_bfloat16* big = g_Ab[2 + which];
    __nv_bfloat16* sml = g_As[2 + which];
    int i = blockIdx.x * blockDim.x + threadIdx.x;
    float4 v = ((const float4*)x)[i];
    __nv_bfloat16 b[4], s[4];
    bf16_split(v.x, b[0], s[0]);
    bf16_split(v.y, b[1], s[1]);
    bf16_split(v.z, b[2], s[2]);
    bf16_split(v.w, b[3], s[3]);
    *(uint2*)&big[(size_t)i * 4] = *(uint2*)b;
    *(uint2*)&sml[(size_t)i * 4] = *(uint2*)s;
}

// ---------------- weight transpose + split -------------------------------------
__global__ void transpose_w(const float* __restrict__ W,
                            __nv_bfloat16* __restrict__ Wb, __nv_bfloat16* __restrict__ Wsml)
{
    __shared__ float t[64][65];
    int h = blockIdx.x, k0 = blockIdx.y * 64;
    const float* Wp = W + (size_t)h * (D_ * DK_);
    #pragma unroll
    for (int i = 0; i < 16; i++) {
        int e = threadIdx.x + i * 256;
        int r = e >> 6, c = e & 63;
        t[r][c] = Wp[(size_t)(k0 + r) * 64 + c];
    }
    __syncthreads();
    #pragma unroll
    for (int i = 0; i < 16; i++) {
        int e = threadIdx.x + i * 256;
        int n = e >> 6, kk = e & 63;
        __nv_bfloat16 big, sml;
        bf16_split(t[kk][n], big, sml);
        size_t off = (size_t)h * (DK_ * D_) + (size_t)n * 512 + k0 + kk;
        Wb[off] = big;
        Wsml[off] = sml;
    }
}

// ---------------- 3xBF16 projection GEMM (stride-144 packed rows) ---------------
// mode 0: fp32 head layout (rows >= M_ROWS go to C2, shifted).
// mode 1: V -> packed V^T operands (g_vd/g_vc). mode 2: RoPE -> split bf16.
#define GSTR 144
#define GA_SZ (128 * GSTR)
#define GB_SZ (64 * GSTR)
#define GSTG (GA_SZ + GB_SZ)
#define GEMM_SMEM (2 * GSTG)

__global__ void __launch_bounds__(256) gemm_bf16(const __nv_bfloat16* __restrict__ Ab,
                                                 const __nv_bfloat16* __restrict__ As,
                                                 const __nv_bfloat16* __restrict__ Bb,
                                                 const __nv_bfloat16* __restrict__ Bs,
                                                 const float* __restrict__ bias,
                                                 float* __restrict__ C,
                                                 float* __restrict__ C2,
                                                 const float* __restrict__ cosA,
                                                 const float* __restrict__ sinA,
                                                 __nv_bfloat16* __restrict__ outB,
                                                 __nv_bfloat16* __restrict__ outS,
                                                 int mode)
{
    extern __shared__ __align__(16) char smraw[];
    uint32_t sb = smem_u32(smraw);
    int tid = threadIdx.x, lane = tid & 31, wid = tid >> 5;
    int warp_m = wid >> 1, warp_n = wid & 1;
    int m0 = blockIdx.x * 128, by = blockIdx.y, n0 = by * 64;

    uint32_t laneA = (uint32_t)((warp_m * 32 + (lane & 7) + ((lane >> 3) & 1) * 8) * GSTR + (lane >> 4) * 16);
    uint32_t laneB = (uint32_t)((warp_n * 32 + (lane & 7) + ((lane >> 3) & 1) * 8) * GSTR + (lane >> 4) * 16);

    float c[8][4];
    #pragma unroll
    for (int i = 0; i < 8; i++)
        #pragma unroll
        for (int j = 0; j < 4; j++) c[i][j] = 0.0f;

    auto load_stage = [&](int s, int k0) {
        uint32_t base = sb + s * GSTG;
        #pragma unroll
        for (int i = 0; i < 4; i++) {
            int e = tid + i * 256, r = e >> 3, cc = e & 7;
            const __nv_bfloat16* src = (cc < 4)
                ? Ab + (size_t)(m0 + r) * 512 + k0 + cc * 8
                : As + (size_t)(m0 + r) * 512 + k0 + (cc - 4) * 8;
            CP_ASYNC16(base + (uint32_t)(r * GSTR + cc * 16), src);
        }
        #pragma unroll
        for (int i = 0; i < 2; i++) {
            int e = tid + i * 256, r = e >> 3, cc = e & 7;
            const __nv_bfloat16* src = (cc < 4)
                ? Bb + (size_t)(n0 + r) * 512 + k0 + cc * 8
                : Bs + (size_t)(n0 + r) * 512 + k0 + (cc - 4) * 8;
            CP_ASYNC16(base + GA_SZ + (uint32_t)(r * GSTR + cc * 16), src);
        }
    };

    auto compute = [&](int s) {
        uint32_t abase = sb + s * GSTG + laneA;
        uint32_t bbase = sb + s * GSTG + GA_SZ + laneB;
        #pragma unroll
        for (int ks = 0; ks < 2; ks++) {
            uint32_t aB[2][4], aS[2][4], bB[2][4], bS[2][4];
            #pragma unroll
            for (int mt = 0; mt < 2; mt++) {
                LDSM_X4(aB[mt][0], aB[mt][1], aB[mt][2], aB[mt][3], abase + mt * (16 * GSTR) + ks * 32);
                LDSM_X4(aS[mt][0], aS[mt][1], aS[mt][2], aS[mt][3], abase + mt * (16 * GSTR) + 64 + ks * 32);
            }
            #pragma unroll
            for (int nt = 0; nt < 2; nt++) {
                LDSM_X4(bB[nt][0], bB[nt][1], bB[nt][2], bB[nt][3], bbase + nt * (16 * GSTR) + ks * 32);
                LDSM_X4(bS[nt][0], bS[nt][1], bS[nt][2], bS[nt][3], bbase + nt * (16 * GSTR) + 64 + ks * 32);
            }
            #pragma unroll
            for (int mt = 0; mt < 2; mt++)
                #pragma unroll
                for (int j = 0; j < 4; j++) {
                    int nt = j >> 1, hh = j & 1;
                    float* cc = c[mt * 4 + j];
                    MMA_BF16(cc, aS[mt][0], aS[mt][1], aS[mt][2], aS[mt][3], bB[nt][hh], bB[nt][2 + hh]);
                    MMA_BF16(cc, aB[mt][0], aB[mt][1], aB[mt][2], aB[mt][3], bS[nt][hh], bS[nt][2 + hh]);
                    MMA_BF16(cc, aB[mt][0], aB[mt][1], aB[mt][2], aB[mt][3], bB[nt][hh], bB[nt][2 + hh]);
                }
        }
    };

    load_stage(0, 0);
    CP_COMMIT();
    for (int ck = 0; ck < 16; ck++) {
        if (ck < 15) {
            load_stage((ck + 1) & 1, (ck + 1) * 32);
            CP_COMMIT();
            CP_WAIT1();
        } else {
            CP_WAIT0();
        }
        __syncthreads();
        compute(ck & 1);
        __syncthreads();
    }

    int r_lane = lane >> 2, c_lane = (lane & 3) * 2;
    #pragma unroll
    for (int i = 0; i < 2; i++) {
        #pragma unroll
        for (int j = 0; j < 4; j++) {
            float* cc = c[i * 4 + j];
            int nc = warp_n * 32 + j * 8 + c_lane;
            int mrow = m0 + warp_m * 32 + i * 16 + r_lane;
            if (mode == 1) {
                float2 bb2 = *(const float2*)&bias[nc];
                #pragma unroll
                for (int rr2 = 0; rr2 < 2; rr2++) {
                    int row = mrow + rr2 * 8;
                    int bi = row >> 10, li = row & 1023;
                    float v0 = cc[rr2 * 2]     + bb2.x;
                    float v1 = cc[rr2 * 2 + 1] + bb2.y;
                    __nv_bfloat16 vb, vs;
                    bf16_split(v0, vb, vs);
                    size_t o0 = (((size_t)bi * DK_) + nc) * L_ + li;
                    uint32_t ub = bf_bits(vb);
                    g_vd[o0] = ub | (ub << 16);
                    g_vc[o0] = bf_bits(vs);
                    bf16_split(v1, vb, vs);
                    size_t o1 = (((size_t)bi * DK_) + nc + 1) * L_ + li;
                    ub = bf_bits(vb);
                    g_vd[o1] = ub | (ub << 16);
                    g_vc[o1] = bf_bits(vs);
                }
                continue;
            }
            float2 bb2 = *(const float2*)&bias[by * 64 + nc];
            #pragma unroll
            for (int rr2 = 0; rr2 < 2; rr2++) {
                int row = mrow + rr2 * 8;
                float v0 = cc[rr2 * 2]     + bb2.x;
                float v1 = cc[rr2 * 2 + 1] + bb2.y;
                float* Cp = C;
                if (mode == 0 && row >= M_ROWS) { Cp = C2; row -= M_ROWS; }
                int bi = row >> 10, li = row & 1023;
                size_t base = ((((size_t)(bi * 8 + by)) << 10) + li) * 64 + nc;
                if (mode == 2) {
                    float2 cv = *(const float2*)&cosA[base];
                    float2 sv = *(const float2*)&sinA[base];
                    float o0 = v0 * cv.x - v1 * sv.x;
                    float o1 = v1 * cv.y + v0 * sv.y;
                    __nv_bfloat16 b0, s0, b1, s1;
                    bf16_split(o0, b0, s0); bf16_split(o1, b1, s1);
                    *(uint32_t*)&outB[base] = bf_pack(b0, b1);
                    *(uint32_t*)&outS[base] = bf_pack(s0, s1);
                } else {
                    float2 o = {v0, v1};
                    *(float2*)&Cp[base] = o;
                }
            }
        }
    }
}

// ---------------- attention: R13 geometry + register-prefetch loads -------------
#define QT  32
#define KT  256
#define SCP 1028
#define STRK 144
#define STRV 528
#define SC_BYTES   (QT * SCP * 4)
#define KREG_OFF   SC_BYTES
#define KREG_BYTES (2 * KT * STRK)
#define VC_OFF     (64 * STRV)
#define QREG_OFF   (KREG_OFF + KREG_BYTES)
#define QB_BYTES   (QT * STRK)
#define ATTN_SMEM  (QREG_OFF + 2 * QB_BYTES)

__global__ void __launch_bounds__(256) attn_kernel(float* __restrict__ attn_out)
{
    extern __shared__ __align__(16) float smf[];
    float* sc  = smf;
    uint32_t* scu = (uint32_t*)smf;
    char*  kreg = (char*)smf + KREG_OFF;
    char*  qreg = (char*)smf + QREG_OFF;

    int tid = threadIdx.x, lane = tid & 31, wid = tid >> 5;
    int q0 = blockIdx.x * QT;
    int h  = blockIdx.y;
    int b  = blockIdx.z;
    size_t bh = (size_t)(b * H_ + h);

    uint32_t skb = smem_u32(kreg), sqb = smem_u32(qreg), ssb = smem_u32(sc);

    {
        int r = tid >> 3, cch = tid & 7;
        const uint4* srcb = (const uint4*)&g_qb[((bh << 10) + q0 + r) * 64];
        const uint4* srcs = (const uint4*)&g_qs[((bh << 10) + q0 + r) * 64];
        *(uint4*)(qreg + r * STRK + cch * 16)            = srcb[cch];
        *(uint4*)(qreg + QB_BYTES + r * STRK + cch * 16) = srcs[cch];
    }

    uint32_t aB0 = sqb + (uint32_t)(((lane & 7) + ((lane >> 3) & 1) * 8) * STRK + (lane >> 4) * 16);
    uint32_t aS0 = aB0 + QB_BYTES;
    uint32_t bB0 = skb + (uint32_t)((wid * 32 + (lane & 7) + ((lane >> 3) & 1) * 8) * STRK + (lane >> 4) * 16);
    uint32_t bS0 = bB0 + (uint32_t)(KT * STRK);

    // register prefetch buffers (reused for K and V phases)
    uint4 pfb[8], pfs[8];

    // preload K chunk 0
    {
        size_t kbase = (bh << 10) * 64;
        #pragma unroll
        for (int i = 0; i < 8; i++) {
            int e = tid + i * 256, r = e >> 3, cch = e & 7;
            pfb[i] = *(const uint4*)&g_kb[kbase + (size_t)r * 64 + cch * 8];
            pfs[i] = *(const uint4*)&g_ks[kbase + (size_t)r * 64 + cch * 8];
        }
    }

    for (int kt = 0; kt < 4; kt++) {
        __syncthreads();
        #pragma unroll
        for (int i = 0; i < 8; i++) {
            int e = tid + i * 256, r = e >> 3, cch = e & 7;
            *(uint4*)(kreg + r * STRK + cch * 16)             = pfb[i];
            *(uint4*)(kreg + KT * STRK + r * STRK + cch * 16) = pfs[i];
        }
        __syncthreads();
        if (kt < 3) {
            size_t kbase = ((bh << 10) + (size_t)(kt + 1) * KT) * 64;
            #pragma unroll
            for (int i = 0; i < 8; i++) {
                int e = tid + i * 256, r = e >> 3, cch = e & 7;
                pfb[i] = *(const uint4*)&g_kb[kbase + (size_t)r * 64 + cch * 8];
                pfs[i] = *(const uint4*)&g_ks[kbase + (size_t)r * 64 + cch * 8];
            }
        }

        float c[2][4][4];
        #pragma unroll
        for (int mt = 0; mt < 2; mt++)
            #pragma unroll
            for (int j = 0; j < 4; j++)
                #pragma unroll
                for (int e = 0; e < 4; e++) c[mt][j][e] = 0.0f;

        #pragma unroll
        for (int ks = 0; ks < 4; ks++) {
            uint32_t aB[2][4], aS[2][4], bB[2][4], bS[2][4];
            #pragma unroll
            for (int mt = 0; mt < 2; mt++) {
                LDSM_X4(aB[mt][0], aB[mt][1], aB[mt][2], aB[mt][3], aB0 + mt * (16 * STRK) + ks * 32);
                LDSM_X4(aS[mt][0], aS[mt][1], aS[mt][2], aS[mt][3], aS0 + mt * (16 * STRK) + ks * 32);
            }
            #pragma unroll
            for (int nt = 0; nt < 2; nt++) {
                LDSM_X4(bB[nt][0], bB[nt][1], bB[nt][2], bB[nt][3], bB0 + nt * (16 * STRK) + ks * 32);
                LDSM_X4(bS[nt][0], bS[nt][1], bS[nt][2], bS[nt][3], bS0 + nt * (16 * STRK) + ks * 32);
            }
            #pragma unroll
            for (int mt = 0; mt < 2; mt++)
                #pragma unroll
                for (int j = 0; j < 4; j++) {
                    int nt = j >> 1, hh = j & 1;
                    float* cc = c[mt][j];
                    MMA_BF16(cc, aS[mt][0], aS[mt][1], aS[mt][2], aS[mt][3], bB[nt][hh], bB[nt][2 + hh]);
                    MMA_BF16(cc, aB[mt][0], aB[mt][1], aB[mt][2], aB[mt][3], bS[nt][hh], bS[nt][2 + hh]);
                    MMA_BF16(cc, aB[mt][0], aB[mt][1], aB[mt][2], aB[mt][3], bB[nt][hh], bB[nt][2 + hh]);
                }
        }
        int rr = lane >> 2, ccl = (lane & 3) * 2;
        #pragma unroll
        for (int mt = 0; mt < 2; mt++)
            #pragma unroll
            for (int j = 0; j < 4; j++) {
                int col = kt * KT + wid * 32 + j * 8 + ccl;
                int row0 = mt * 16 + rr;
                float2 o0 = {c[mt][j][0] * 0.125f, c[mt][j][1] * 0.125f};
                float2 o1 = {c[mt][j][2] * 0.125f, c[mt][j][3] * 0.125f};
                *(float2*)&sc[row0 * SCP + col]       = o0;
                *(float2*)&sc[(row0 + 8) * SCP + col] = o1;
            }
    }
    __syncthreads();

    // preload V chunk 0 (latency hidden by softmax)
    {
        const uint32_t* vdg = g_vd + ((size_t)b * DK_) * L_;
        const uint32_t* vcg = g_vc + ((size_t)b * DK_) * L_;
        #pragma unroll
        for (int i = 0; i < 8; i++) {
            int e = tid + i * 256, r = e >> 5, ch = e & 31;
            pfb[i] = *(const uint4*)(vdg + (size_t)r * L_ + ch * 4);
            pfs[i] = *(const uint4*)(vcg + (size_t)r * L_ + ch * 4);
        }
    }

    for (int rr = wid * 4; rr < wid * 4 + 4; rr++) {
        float vals[32];
        float mx = -1e30f;
        #pragma unroll
        for (int j = 0; j < 32; j++) {
            vals[j] = sc[rr * SCP + lane + 32 * j];
            mx = fmaxf(mx, vals[j]);
        }
        #pragma unroll
        for (int o = 16; o; o >>= 1) mx = fmaxf(mx, __shfl_xor_sync(0xFFFFFFFFu, mx, o));
        float s = 0.0f;
        #pragma unroll
        for (int j = 0; j < 32; j++) { vals[j] = __expf(vals[j] - mx); s += vals[j]; }
        #pragma unroll
        for (int o = 16; o; o >>= 1) s += __shfl_xor_sync(0xFFFFFFFFu, s, o);
        float inv = 1.0f / s;
        size_t obase = (((size_t)(b * L_ + q0 + rr) * H_ + h) << 10);
        #pragma unroll
        for (int j = 0; j < 32; j++) {
            float p = vals[j] * inv;
            attn_out[obase + lane + 32 * j] = p;
            __nv_bfloat16 pb, ps;
            bf16_split(p, pb, ps);
            scu[rr * SCP + lane + 32 * j] = bf_pack(pb, ps);
        }
    }

    int mt = wid >> 2, nt = wid & 3;
    float acc[2][4];
    #pragma unroll
    for (int j = 0; j < 2; j++)
        #pragma unroll
        for (int e = 0; e < 4; e++) acc[j][e] = 0.0f;

    uint32_t aP0 = ssb + (uint32_t)((mt * 16 + (lane & 7) + ((lane >> 3) & 1) * 8) * (SCP * 4) + (lane >> 4) * 16);
    uint32_t vD0 = skb + (uint32_t)((nt * 16 + (lane & 7) + ((lane >> 3) & 1) * 8) * STRV + (lane >> 4) * 16);
    uint32_t vC0 = vD0 + (uint32_t)VC_OFF;

    for (int vt = 0; vt < 8; vt++) {
        __syncthreads();
        #pragma unroll
        for (int i = 0; i < 8; i++) {
            int e = tid + i * 256, r = e >> 5, ch = e & 31;
            *(uint4*)(kreg + r * STRV + ch * 16)          = pfb[i];
            *(uint4*)(kreg + VC_OFF + r * STRV + ch * 16) = pfs[i];
        }
        __syncthreads();
        if (vt < 7) {
            const uint32_t* vdg = g_vd + ((size_t)b * DK_) * L_ + (vt + 1) * 128;
            const uint32_t* vcg = g_vc + ((size_t)b * DK_) * L_ + (vt + 1) * 128;
            #pragma unroll
            for (int i = 0; i < 8; i++) {
                int e = tid + i * 256, r = e >> 5, ch = e & 31;
                pfb[i] = *(const uint4*)(vdg + (size_t)r * L_ + ch * 4);
                pfs[i] = *(const uint4*)(vcg + (size_t)r * L_ + ch * 4);
            }
        }
        #pragma unroll
        for (int st = 0; st < 16; st++) {
            uint32_t a[4], bd[4], bc[4];
            LDSM_X4(a[0], a[1], a[2], a[3], aP0 + (uint32_t)(vt * 512 + st * 32));
            LDSM_X4(bd[0], bd[1], bd[2], bd[3], vD0 + st * 32);
            LDSM_X4(bc[0], bc[1], bc[2], bc[3], vC0 + st * 32);
            #pragma unroll
            for (int j = 0; j < 2; j++) {
                MMA_BF16(acc[j], a[0], a[1], a[2], a[3], bd[j], bd[2 + j]);
                MMA_BF16(acc[j], a[0], a[1], a[2], a[3], bc[j], bc[2 + j]);
            }
        }
    }
    {
        int rr = lane >> 2, cl = (lane & 3) * 2;
        #pragma unroll
        for (int j = 0; j < 2; j++) {
            int col = nt * 16 + j * 8 + cl;
            int row0 = mt * 16 + rr;
            float2 o0 = {acc[j][0], acc[j][1]};
            float2 o1 = {acc[j][2], acc[j][3]};
            *(float2*)&g_head[((bh << 10) + q0 + row0) * 64 + col]     = o0;
            *(float2*)&g_head[((bh << 10) + q0 + row0 + 8) * 64 + col] = o1;
        }
    }
}

// ---------------- final: out = mean_h(head) @ Wh ------------------------------
__global__ void __launch_bounds__(256) out_kernel(const float* __restrict__ Wh,
                                                  float* __restrict__ out)
{
    extern __shared__ __align__(16) float sm2[];
    __shared__ float hm[8][64];
    int tid = threadIdx.x;
    int m0 = blockIdx.x * 8;
    int bb = m0 >> 10;
    int l0 = m0 & 1023;

    #pragma unroll
    for (int i = 0; i < 32; i++) {
        int e = tid + i * 256;
        ((float4*)sm2)[e] = ((const float4*)Wh)[e];
    }
    #pragma unroll
    for (int i = 0; i < 2; i++) {
        int e = tid + i * 256;
        int r = e >> 6, kk = e & 63;
        float s = 0.0f;
        #pragma unroll
        for (int hh = 0; hh < 8; hh++)
            s += g_head[(((size_t)(bb * H_ + hh) << 10) + l0 + r) * 64 + kk];
        hm[r][kk] = s * 0.125f;
    }
    __syncthreads();

    int ty = tid >> 6;
    int tx = tid & 63;
    float acc[2][8];
    #pragma unroll
    for (int i = 0; i < 2; i++)
        #pragma unroll
        for (int j = 0; j < 8; j++) acc[i][j] = 0.0f;
    #pragma unroll 8
    for (int d = 0; d < 64; d++) {
        float a0 = hm[ty * 2][d];
        float a1 = hm[ty * 2 + 1][d];
        float4 w0 = *(float4*)&sm2[d * 512 + tx * 8];
        float4 w1 = *(float4*)&sm2[d * 512 + tx * 8 + 4];
        acc[0][0] += a0 * w0.x; acc[0][1] += a0 * w0.y; acc[0][2] += a0 * w0.z; acc[0][3] += a0 * w0.w;
        acc[0][4] += a0 * w1.x; acc[0][5] += a0 * w1.y; acc[0][6] += a0 * w1.z; acc[0][7] += a0 * w1.w;
        acc[1][0] += a1 * w0.x; acc[1][1] += a1 * w0.y; acc[1][2] += a1 * w0.z; acc[1][3] += a1 * w0.w;
        acc[1][4] += a1 * w1.x; acc[1][5] += a1 * w1.y; acc[1][6] += a1 * w1.z; acc[1][7] += a1 * w1.w;
    }
    #pragma unroll
    for (int i = 0; i < 2; i++) {
        int m = m0 + ty * 2 + i;
        float4 o0 = {acc[i][0], acc[i][1], acc[i][2], acc[i][3]};
        float4 o1 = {acc[i][4], acc[i][5], acc[i][6], acc[i][7]};
        *(float4*)&out[(size_t)m * 512 + tx * 8]     = o0;
        *(float4*)&out[(size_t)m * 512 + tx * 8 + 4] = o1;
    }
}

// ---------------- launch ------------------------------------------------------
extern "C" void kernel_launch(void* const* d_in, const int* in_sizes, int n_in,
                              void* d_out, int out_size)
{
    const float* sat     = (const float*)d_in[0];
    const float* satpos  = (const float*)d_in[1];
    const float* ts      = (const float*)d_in[2];
    const float* tspos   = (const float*)d_in[3];
    const float* lsg     = (const float*)d_in[4];
    const float* lsb     = (const float*)d_in[5];
    const float* ltg     = (const float*)d_in[6];
    const float* ltb     = (const float*)d_in[7];
    const float* Wv      = (const float*)d_in[8];
    const float* bv      = (const float*)d_in[9];
    const float* Wq      = (const float*)d_in[10];
    const float* bq      = (const float*)d_in[11];
    const float* Wk      = (const float*)d_in[12];
    const float* bk      = (const float*)d_in[13];
    const float* Wsat    = (const float*)d_in[14];
    const float* bsat    = (const float*)d_in[15];
    const float* Wts     = (const float*)d_in[16];
    const float* bts     = (const float*)d_in[17];
    const float* Wh      = (const float*)d_in[18];

    float* out      = (float*)d_out;
    float* attn_out = out + OUT0_ELEMS;

    float *p_ss, *p_cs, *p_st, *p_ct;
    __nv_bfloat16 *p_Ab, *p_As, *p_Wb, *p_Ws, *p_WVb, *p_WVs;
    __nv_bfloat16 *p_qb, *p_qs, *p_kb, *p_ks;
    cudaGetSymbolAddress((void**)&p_ss,  g_ss);
    cudaGetSymbolAddress((void**)&p_cs,  g_cs);
    cudaGetSymbolAddress((void**)&p_st,  g_st);
    cudaGetSymbolAddress((void**)&p_ct,  g_ct);
    cudaGetSymbolAddress((void**)&p_Ab,  g_Ab);
    cudaGetSymbolAddress((void**)&p_As,  g_As);
    cudaGetSymbolAddress((void**)&p_Wb,  g_Wb);
    cudaGetSymbolAddress((void**)&p_Ws,  g_Ws);
    cudaGetSymbolAddress((void**)&p_WVb, g_WVb);
    cudaGetSymbolAddress((void**)&p_WVs, g_WVs);
    cudaGetSymbolAddress((void**)&p_qb,  g_qb);
    cudaGetSymbolAddress((void**)&p_qs,  g_qs);
    cudaGetSymbolAddress((void**)&p_kb,  g_kb);
    cudaGetSymbolAddress((void**)&p_ks,  g_ks);

    cudaFuncSetAttribute(attn_kernel, cudaFuncAttributeMaxDynamicSharedMemorySize, ATTN_SMEM);
    cudaFuncSetAttribute(out_kernel,  cudaFuncAttributeMaxDynamicSharedMemorySize, 64 * 512 * 4);
    cudaFuncSetAttribute(gemm_bf16,   cudaFuncAttributeMaxDynamicSharedMemorySize, GEMM_SMEM);

    const size_t WSZ = (size_t)H_ * DK_ * D_;
    const size_t TE  = (size_t)TOK_ELEMS;

    // 1. LayerNorms
    ln_kernel<<<2 * M_ROWS, 128>>>(sat, ts, lsg, lsb, ltg, ltb);

    // 2. split pos embeddings
    split4_kernel<<<dim3(TOK_ELEMS / 1024, 4), 256>>>(satpos, satpos + TOK_ELEMS,
                                                      tspos, tspos + TOK_ELEMS);

    // 3. transpose + split weights
    transpose_w<<<dim3(8, 8), 256>>>(Wq,   p_Wb + 0 * WSZ, p_Ws + 0 * WSZ);
    transpose_w<<<dim3(8, 8), 256>>>(Wk,   p_Wb + 1 * WSZ, p_Ws + 1 * WSZ);
    transpose_w<<<dim3(8, 8), 256>>>(Wsat, p_Wb + 2 * WSZ, p_Ws + 2 * WSZ);
    transpose_w<<<dim3(8, 8), 256>>>(Wts,  p_Wb + 3 * WSZ, p_Ws + 3 * WSZ);
    transpose_w<<<dim3(1, 8), 256>>>(Wv,   p_WVb, p_WVs);

    // 4. sin/cos projections — batched pairs (doubled M; contiguous A halves)
    dim3 gg2(2 * M_ROWS / 128, 8);
    gemm_bf16<<<gg2, 256, GEMM_SMEM>>>(p_Ab + 2 * TE, p_As + 2 * TE, p_Wb + 2 * WSZ, p_Ws + 2 * WSZ, bsat, p_ss, p_cs, nullptr, nullptr, nullptr, nullptr, 0);
    gemm_bf16<<<gg2, 256, GEMM_SMEM>>>(p_Ab + 4 * TE, p_As + 4 * TE, p_Wb + 3 * WSZ, p_Ws + 3 * WSZ, bts,  p_st, p_ct, nullptr, nullptr, nullptr, nullptr, 0);

    // 5. q/k projections with fused RoPE epilogue -> split bf16
    dim3 gg(M_ROWS / 128, 8);
    gemm_bf16<<<gg, 256, GEMM_SMEM>>>(p_Ab + 1 * TE, p_As + 1 * TE, p_Wb + 0 * WSZ, p_Ws + 0 * WSZ, bq, nullptr, nullptr, p_ct, p_st, p_qb, p_qs, 2);
    gemm_bf16<<<gg, 256, GEMM_SMEM>>>(p_Ab + 0 * TE, p_As + 0 * TE, p_Wb + 1 * WSZ, p_Ws + 1 * WSZ, bk, nullptr, nullptr, p_cs, p_ss, p_kb, p_ks, 2);

    // 6. V projection with fused split/pack/transpose epilogue
    gemm_bf16<<<dim3(M_ROWS / 128, 1), 256, GEMM_SMEM>>>(p_Ab + 0 * TE, p_As + 0 * TE, p_WVb, p_WVs, bv, nullptr, nullptr, nullptr, nullptr, nullptr, nullptr, 1);

    // 7. attention (register-prefetch loads)
    dim3 ga(L_ / QT, H_, B_);
    attn_kernel<<<ga, 256, ATTN_SMEM>>>(attn_out);

    // 8. out = mean_h(head) @ Wh
    out_kernel<<<M_ROWS / 8, 256, 64 * 512 * 4>>>(Wh, out);
}